// round 1
// baseline (speedup 1.0000x reference)
#include <cuda_runtime.h>
#include <math.h>
#include <stdint.h>

#define NN 100000
#define NE 320000
#define NG 512
#define FDIM 256
#define FOUT 128

// ---------------- scratch (static device memory; no allocation) ----------------
__device__ float g_bufA[(size_t)NN * FDIM];   // layer input / aggregation output
__device__ float g_bufH[(size_t)NN * FDIM];   // GEMM output (pre-aggregation)
__device__ float g_dinv[NN];                  // deg accumulator, then rsqrt(deg)
__device__ int   g_src[NE];
__device__ int   g_dst[NE];
__device__ int   g_batch[NN];
__device__ float g_pool[NG * FDIM];
__device__ float g_cnt[NG];
__device__ int   g_flag;                      // 1 = indices are int64, 0 = int32

// ---------------- index dtype detection + conversion ----------------
__global__ void k_detect(const void* e) {
    const long long* p = (const long long*)e;
    int is64 = 1;
    for (int i = 0; i < 16; i++) {
        long long v = p[i];
        if (v < 0 || v >= NN) is64 = 0;
    }
    g_flag = is64;
}

__global__ void k_convert(const void* e, const void* b) {
    int i = blockIdx.x * blockDim.x + threadIdx.x;
    int f64 = g_flag;
    if (i < NE) {
        if (f64) {
            const long long* p = (const long long*)e;
            g_src[i] = (int)p[i];
            g_dst[i] = (int)p[NE + i];
        } else {
            const int* p = (const int*)e;
            g_src[i] = p[i];
            g_dst[i] = p[NE + i];
        }
    }
    if (i < NN) {
        if (f64) g_batch[i] = (int)((const long long*)b)[i];
        else     g_batch[i] = ((const int*)b)[i];
    }
}

// ---------------- degree / symmetric norm ----------------
__global__ void k_deg_init() {
    int i = blockIdx.x * blockDim.x + threadIdx.x;
    if (i < NN) g_dinv[i] = 1.0f;  // self-loop contributes 1 to in-degree
}
__global__ void k_deg_count() {
    int i = blockIdx.x * blockDim.x + threadIdx.x;
    if (i < NE) atomicAdd(&g_dinv[g_dst[i]], 1.0f);
}
__global__ void k_dinv() {
    int i = blockIdx.x * blockDim.x + threadIdx.x;
    if (i < NN) g_dinv[i] = rsqrtf(g_dinv[i]);
}

// ---------------- SGEMM: C[M,N] = act(A[M,K]) @ B[K,N]  (optional ReLU on A) ----
#define BM 128
#define BN 128
#define BK 16

__global__ __launch_bounds__(256) void k_sgemm(
    const float* __restrict__ A, const float* __restrict__ B,
    float* __restrict__ C, int M, int K, int N, int relu)
{
    __shared__ float As[BK][BM + 4];
    __shared__ float Bs[BK][BN];

    int bm = blockIdx.y * BM;
    int bn = blockIdx.x * BN;
    int tid = threadIdx.x;
    int tr = tid >> 4;   // 0..15
    int tc = tid & 15;   // 0..15

    float acc[8][8];
#pragma unroll
    for (int i = 0; i < 8; i++)
#pragma unroll
        for (int j = 0; j < 8; j++) acc[i][j] = 0.0f;

    for (int k0 = 0; k0 < K; k0 += BK) {
        // A tile: 128x16, float4 along K
#pragma unroll
        for (int p = 0; p < 2; p++) {
            int idx = tid + p * 256;       // 0..511
            int row = idx >> 2;            // 0..127
            int kc  = (idx & 3) << 2;      // 0,4,8,12
            float4 v = make_float4(0.f, 0.f, 0.f, 0.f);
            int gr = bm + row;
            if (gr < M) v = *(const float4*)(A + (size_t)gr * K + k0 + kc);
            if (relu) {
                v.x = fmaxf(v.x, 0.f); v.y = fmaxf(v.y, 0.f);
                v.z = fmaxf(v.z, 0.f); v.w = fmaxf(v.w, 0.f);
            }
            As[kc + 0][row] = v.x; As[kc + 1][row] = v.y;
            As[kc + 2][row] = v.z; As[kc + 3][row] = v.w;
        }
        // B tile: 16x128
#pragma unroll
        for (int p = 0; p < 2; p++) {
            int idx = tid + p * 256;       // 0..511
            int row = idx >> 5;            // 0..15
            int col = (idx & 31) << 2;     // 0..124
            *(float4*)&Bs[row][col] =
                *(const float4*)(B + (size_t)(k0 + row) * N + bn + col);
        }
        __syncthreads();

#pragma unroll
        for (int kk = 0; kk < BK; kk++) {
            float a[8], bb[8];
            *(float4*)&a[0]  = *(const float4*)&As[kk][tr * 8];
            *(float4*)&a[4]  = *(const float4*)&As[kk][tr * 8 + 4];
            *(float4*)&bb[0] = *(const float4*)&Bs[kk][tc * 8];
            *(float4*)&bb[4] = *(const float4*)&Bs[kk][tc * 8 + 4];
#pragma unroll
            for (int i = 0; i < 8; i++)
#pragma unroll
                for (int j = 0; j < 8; j++) acc[i][j] += a[i] * bb[j];
        }
        __syncthreads();
    }

#pragma unroll
    for (int i = 0; i < 8; i++) {
        int row = bm + tr * 8 + i;
        if (row < M) {
            float* c = C + (size_t)row * N + bn + tc * 8;
            *(float4*)c       = make_float4(acc[i][0], acc[i][1], acc[i][2], acc[i][3]);
            *(float4*)(c + 4) = make_float4(acc[i][4], acc[i][5], acc[i][6], acc[i][7]);
        }
    }
}

// ---------------- aggregation: init (self-loop + bias), then edge scatter -------
__global__ void k_init_out(const float* __restrict__ bias) {
    int i = blockIdx.x * blockDim.x + threadIdx.x;  // over NN*64 float4 chunks
    if (i >= NN * 64) return;
    int node = i >> 6;
    int c = i & 63;
    float di = g_dinv[node];
    float nrm = di * di;
    float4 h = *(const float4*)(g_bufH + (size_t)node * FDIM + c * 4);
    float4 b = *(const float4*)(bias + c * 4);
    float4 o;
    o.x = h.x * nrm + b.x;
    o.y = h.y * nrm + b.y;
    o.z = h.z * nrm + b.z;
    o.w = h.w * nrm + b.w;
    *(float4*)(g_bufA + (size_t)node * FDIM + c * 4) = o;
}

__global__ void k_scatter() {
    int gid = blockIdx.x * blockDim.x + threadIdx.x;
    int e = gid >> 5;
    int lane = gid & 31;
    if (e >= NE) return;
    int s = g_src[e], d = g_dst[e];
    float nrm = g_dinv[s] * g_dinv[d];
    const float4* hs = (const float4*)(g_bufH + (size_t)s * FDIM);
    float* od = g_bufA + (size_t)d * FDIM;
#pragma unroll
    for (int p = 0; p < 2; p++) {
        int c = lane + p * 32;
        float4 v = hs[c];
        atomicAdd(od + c * 4 + 0, v.x * nrm);
        atomicAdd(od + c * 4 + 1, v.y * nrm);
        atomicAdd(od + c * 4 + 2, v.z * nrm);
        atomicAdd(od + c * 4 + 3, v.w * nrm);
    }
}

// ---------------- pooling (ReLU fused) + FC ----------------
__global__ void k_pool_zero() {
    int i = blockIdx.x * blockDim.x + threadIdx.x;
    if (i < NG * FDIM) g_pool[i] = 0.0f;
    if (i < NG) g_cnt[i] = 0.0f;
}

__global__ void k_pool() {
    int i = blockIdx.x * blockDim.x + threadIdx.x;  // NN*64 chunks
    if (i >= NN * 64) return;
    int node = i >> 6;
    int c = i & 63;
    int g = g_batch[node];
    float4 v = *(const float4*)(g_bufA + (size_t)node * FDIM + c * 4);
    float* pp = g_pool + (size_t)g * FDIM + c * 4;
    atomicAdd(pp + 0, fmaxf(v.x, 0.f));
    atomicAdd(pp + 1, fmaxf(v.y, 0.f));
    atomicAdd(pp + 2, fmaxf(v.z, 0.f));
    atomicAdd(pp + 3, fmaxf(v.w, 0.f));
    if (c == 0) atomicAdd(&g_cnt[g], 1.0f);
}

__global__ void k_fc(const float* __restrict__ Wfc, const float* __restrict__ bfc,
                     float* __restrict__ out) {
    __shared__ float sp[FDIM];
    int g = blockIdx.x;
    float inv = 1.0f / fmaxf(g_cnt[g], 1.0f);
    for (int f = threadIdx.x; f < FDIM; f += 128)
        sp[f] = g_pool[(size_t)g * FDIM + f] * inv;
    __syncthreads();
    int j = threadIdx.x;  // 0..127
    float acc = bfc[j];
#pragma unroll 4
    for (int f = 0; f < FDIM; f++) acc += sp[f] * Wfc[(size_t)f * FOUT + j];
    out[(size_t)g * FOUT + j] = acc;
}

// ---------------- launch ----------------
extern "C" void kernel_launch(void* const* d_in, const int* in_sizes, int n_in,
                              void* d_out, int out_size) {
    (void)in_sizes; (void)n_in; (void)out_size;
    const float* x   = (const float*)d_in[0];
    const void*  ei  = d_in[1];
    const void*  bt  = d_in[2];
    const float* W1  = (const float*)d_in[3];
    const float* b1  = (const float*)d_in[4];
    const float* W2  = (const float*)d_in[5];
    const float* b2  = (const float*)d_in[6];
    const float* W3  = (const float*)d_in[7];
    const float* b3  = (const float*)d_in[8];
    const float* Wfc = (const float*)d_in[9];
    const float* bfc = (const float*)d_in[10];
    float* out = (float*)d_out;

    float *bufA = nullptr, *bufH = nullptr;
    cudaGetSymbolAddress((void**)&bufA, g_bufA);
    cudaGetSymbolAddress((void**)&bufH, g_bufH);

    // index prep
    k_detect<<<1, 1>>>(ei);
    k_convert<<<(NE + 255) / 256, 256>>>(ei, bt);
    k_deg_init<<<(NN + 255) / 256, 256>>>();
    k_deg_count<<<(NE + 255) / 256, 256>>>();
    k_dinv<<<(NN + 255) / 256, 256>>>();

    dim3 gemm_grid(FDIM / BN, (NN + BM - 1) / BM);
    int n_init = (NN * 64 + 255) / 256;
    int n_scat = (NE * 32 + 255) / 256;

    // layer 1 (K=128, input is raw x)
    k_sgemm<<<gemm_grid, 256>>>(x, W1, bufH, NN, 128, FDIM, 0);
    k_init_out<<<n_init, 256>>>(b1);
    k_scatter<<<n_scat, 256>>>();
    // layer 2 (K=256, ReLU fused into A load)
    k_sgemm<<<gemm_grid, 256>>>(bufA, W2, bufH, NN, FDIM, FDIM, 1);
    k_init_out<<<n_init, 256>>>(b2);
    k_scatter<<<n_scat, 256>>>();
    // layer 3
    k_sgemm<<<gemm_grid, 256>>>(bufA, W3, bufH, NN, FDIM, FDIM, 1);
    k_init_out<<<n_init, 256>>>(b3);
    k_scatter<<<n_scat, 256>>>();

    // pool + fc
    k_pool_zero<<<(NG * FDIM + 255) / 256, 256>>>();
    k_pool<<<n_init, 256>>>();
    k_fc<<<NG, 128>>>(Wfc, bfc, out);
}

// round 4
// speedup vs baseline: 1.2732x; 1.2732x over previous
#include <cuda_runtime.h>
#include <cuda_bf16.h>
#include <math.h>
#include <stdint.h>

#define NN 100000
#define NE 320000
#define NG 512
#define FDIM 256
#define FOUT 128

// ---------------- scratch (static device memory; no allocation) ----------------
__device__ __align__(16) float g_buf0[(size_t)NN * FDIM];   // node features ping
__device__ __align__(16) float g_buf1[(size_t)NN * FDIM];   // node features pong
__device__ __align__(16) float g_bufH[(size_t)NN * FDIM];   // GEMM output (scatter source)
__device__ float g_dinv[NN];
__device__ int   g_src[NE];
__device__ int   g_dst[NE];
__device__ int   g_batch[NN];
__device__ float g_pool[NG * FDIM];
__device__ float g_cnt[NG];
__device__ int   g_flag;
__device__ __align__(16) __nv_bfloat16 g_wt_hi[256 * 256];  // W^T split hi  [N][K]
__device__ __align__(16) __nv_bfloat16 g_wt_lo[256 * 256];  // W^T split lo  [N][K]

// ---------------- helpers ----------------
__device__ __forceinline__ uint32_t smem_u32(const void* p) {
    uint32_t a;
    asm("{ .reg .u64 t; cvta.to.shared.u64 t, %1; cvt.u32.u64 %0, t; }" : "=r"(a) : "l"(p));
    return a;
}

__device__ __forceinline__ void ldmat_x4(uint32_t* r, uint32_t addr) {
    asm volatile("ldmatrix.sync.aligned.m8n8.x4.shared.b16 {%0,%1,%2,%3}, [%4];"
                 : "=r"(r[0]), "=r"(r[1]), "=r"(r[2]), "=r"(r[3]) : "r"(addr));
}

__device__ __forceinline__ void mma16816(float* c, const uint32_t* a, const uint32_t* b) {
    asm volatile("mma.sync.aligned.m16n8k16.row.col.f32.bf16.bf16.f32 "
                 "{%0,%1,%2,%3}, {%4,%5,%6,%7}, {%8,%9}, {%0,%1,%2,%3};"
                 : "+f"(c[0]), "+f"(c[1]), "+f"(c[2]), "+f"(c[3])
                 : "r"(a[0]), "r"(a[1]), "r"(a[2]), "r"(a[3]), "r"(b[0]), "r"(b[1]));
}

// ---------------- index dtype detection + conversion ----------------
__global__ void k_detect(const void* e) {
    const long long* p = (const long long*)e;
    int is64 = 1;
    for (int i = 0; i < 16; i++) {
        long long v = p[i];
        if (v < 0 || v >= NN) is64 = 0;
    }
    g_flag = is64;
}

__global__ void k_convert(const void* e, const void* b) {
    int i = blockIdx.x * blockDim.x + threadIdx.x;
    int f64 = g_flag;
    if (i < NE) {
        if (f64) {
            const long long* p = (const long long*)e;
            g_src[i] = (int)p[i];
            g_dst[i] = (int)p[NE + i];
        } else {
            const int* p = (const int*)e;
            g_src[i] = p[i];
            g_dst[i] = p[NE + i];
        }
    }
    if (i < NN) {
        if (f64) g_batch[i] = (int)((const long long*)b)[i];
        else     g_batch[i] = ((const int*)b)[i];
    }
}

__global__ void k_deg_init() {
    int i = blockIdx.x * blockDim.x + threadIdx.x;
    if (i < NN) g_dinv[i] = 1.0f;
}
__global__ void k_deg_count() {
    int i = blockIdx.x * blockDim.x + threadIdx.x;
    if (i < NE) atomicAdd(&g_dinv[g_dst[i]], 1.0f);
}
__global__ void k_dinv() {
    int i = blockIdx.x * blockDim.x + threadIdx.x;
    if (i < NN) g_dinv[i] = rsqrtf(g_dinv[i]);
}

// ---------------- weight transpose + bf16 split: W[K,256] -> Wt_hi/lo[256,K] ----
__global__ void k_wsplit(const float* __restrict__ W, int K) {
    int i = blockIdx.x * blockDim.x + threadIdx.x;
    if (i >= K * 256) return;
    int k = i >> 8, n = i & 255;
    float v = W[i];
    __nv_bfloat16 h = __float2bfloat16(v);
    float r = v - __bfloat162float(h);
    g_wt_hi[(size_t)n * K + k] = h;
    g_wt_lo[(size_t)n * K + k] = __float2bfloat16(r);
}

// ---------------- mma.sync split-bf16 GEMM + fused epilogue ----------------
// CTA tile 128x128; warp tile 64x32 (2x4 warps); K-chunk 64.
// outH = act(A) @ W ; outA = outH * dinv^2 + bias    (outA MUST NOT alias A)
#define TSTR 72              // smem row stride (bf16 elems), conflict-free
#define SA_HI 0
#define SA_LO 18432
#define SB_HI 36864
#define SB_LO 55296
#define GEMM_SMEM 73728

__global__ void __launch_bounds__(256, 1)
k_gemm(const float* __restrict__ A, const float* __restrict__ bias,
       float* __restrict__ outH, float* __restrict__ outA, int M, int K, int relu)
{
    extern __shared__ char smem[];
    uint32_t sb = smem_u32(smem);
    int tid = threadIdx.x;
    int wid = tid >> 5;
    int lane = tid & 31;
    int bm = blockIdx.x * 128;
    int n0 = blockIdx.y * 128;
    int wm = (wid >> 2) * 64;    // warp row offset in CTA tile
    int wn = (wid & 3) * 32;     // warp col offset in CTA tile

    float acc[4][4][4];
#pragma unroll
    for (int mi = 0; mi < 4; mi++)
#pragma unroll
        for (int ni = 0; ni < 4; ni++)
#pragma unroll
            for (int q = 0; q < 4; q++) acc[mi][ni][q] = 0.0f;

    const int nchunks = K >> 6;
    for (int ch = 0; ch < nchunks; ch++) {
        int k0 = ch << 6;

        // ---- fill A: 128 rows x 64 f32 -> bf16 hi/lo ----
#pragma unroll
        for (int it = 0; it < 8; it++) {
            int idx = tid + it * 256;      // 0..2047
            int row = idx >> 4;
            int g   = idx & 15;
            float4 v = make_float4(0.f, 0.f, 0.f, 0.f);
            int gr = bm + row;
            if (gr < M) v = *(const float4*)(A + (size_t)gr * K + k0 + g * 4);
            if (relu) {
                v.x = fmaxf(v.x, 0.f); v.y = fmaxf(v.y, 0.f);
                v.z = fmaxf(v.z, 0.f); v.w = fmaxf(v.w, 0.f);
            }
            __nv_bfloat16 h0 = __float2bfloat16(v.x), h1 = __float2bfloat16(v.y);
            __nv_bfloat16 h2 = __float2bfloat16(v.z), h3 = __float2bfloat16(v.w);
            __nv_bfloat16 l0 = __float2bfloat16(v.x - __bfloat162float(h0));
            __nv_bfloat16 l1 = __float2bfloat16(v.y - __bfloat162float(h1));
            __nv_bfloat16 l2 = __float2bfloat16(v.z - __bfloat162float(h2));
            __nv_bfloat16 l3 = __float2bfloat16(v.w - __bfloat162float(h3));
            uint2 hp, lp;
            hp.x = ((uint32_t)__bfloat16_as_ushort(h1) << 16) | __bfloat16_as_ushort(h0);
            hp.y = ((uint32_t)__bfloat16_as_ushort(h3) << 16) | __bfloat16_as_ushort(h2);
            lp.x = ((uint32_t)__bfloat16_as_ushort(l1) << 16) | __bfloat16_as_ushort(l0);
            lp.y = ((uint32_t)__bfloat16_as_ushort(l3) << 16) | __bfloat16_as_ushort(l2);
            uint32_t off = (uint32_t)(row * TSTR + g * 4) * 2;
            *(uint2*)(smem + SA_HI + off) = hp;
            *(uint2*)(smem + SA_LO + off) = lp;
        }
        // ---- fill B: Wt hi/lo, 128 rows x 64 bf16 each ----
#pragma unroll
        for (int it = 0; it < 4; it++) {
            int idx = tid + it * 256;      // 0..1023
            int row = idx >> 3;
            int g   = idx & 7;
            uint32_t off = (uint32_t)(row * TSTR + g * 8) * 2;
            *(uint4*)(smem + SB_HI + off) =
                *(const uint4*)(g_wt_hi + (size_t)(n0 + row) * K + k0 + g * 8);
            *(uint4*)(smem + SB_LO + off) =
                *(const uint4*)(g_wt_lo + (size_t)(n0 + row) * K + k0 + g * 8);
        }
        __syncthreads();

#pragma unroll
        for (int ks = 0; ks < 4; ks++) {
            int kk = ks * 16;
            uint32_t ah[4][4], al[4][4], bh[2][4], bl[2][4];
            int arow = (lane & 15);
            int acol = kk + ((lane >> 4) << 3);
#pragma unroll
            for (int mi = 0; mi < 4; mi++) {
                uint32_t off = (uint32_t)((wm + mi * 16 + arow) * TSTR + acol) * 2;
                ldmat_x4(ah[mi], sb + SA_HI + off);
                ldmat_x4(al[mi], sb + SA_LO + off);
            }
            int brow = ((lane >> 4) << 3) + (lane & 7);
            int bcol = kk + ((lane >> 3) & 1) * 8;
#pragma unroll
            for (int j = 0; j < 2; j++) {
                uint32_t off = (uint32_t)((wn + 16 * j + brow) * TSTR + bcol) * 2;
                ldmat_x4(bh[j], sb + SB_HI + off);
                ldmat_x4(bl[j], sb + SB_LO + off);
            }
#pragma unroll
            for (int mi = 0; mi < 4; mi++) {
#pragma unroll
                for (int ni = 0; ni < 4; ni++) {
                    const uint32_t* bhp = &bh[ni >> 1][(ni & 1) * 2];
                    const uint32_t* blp = &bl[ni >> 1][(ni & 1) * 2];
                    mma16816(acc[mi][ni], ah[mi], bhp);
                    mma16816(acc[mi][ni], ah[mi], blp);
                    mma16816(acc[mi][ni], al[mi], bhp);
                }
            }
        }
        __syncthreads();
    }

    // ---- epilogue: fused bias + self-loop ----
    int g = lane >> 2, tg = lane & 3;
#pragma unroll
    for (int mi = 0; mi < 4; mi++) {
        int r0 = bm + wm + mi * 16 + g;
        int r1 = r0 + 8;
        float nr0 = 0.f, nr1 = 0.f;
        if (r0 < M) { nr0 = g_dinv[r0]; nr0 *= nr0; }
        if (r1 < M) { nr1 = g_dinv[r1]; nr1 *= nr1; }
#pragma unroll
        for (int ni = 0; ni < 4; ni++) {
            int col = n0 + wn + ni * 8 + tg * 2;
            float2 bv = *(const float2*)(bias + col);
            float* c = acc[mi][ni];
            if (r0 < M) {
                *(float2*)(outH + (size_t)r0 * 256 + col) = make_float2(c[0], c[1]);
                *(float2*)(outA + (size_t)r0 * 256 + col) =
                    make_float2(c[0] * nr0 + bv.x, c[1] * nr0 + bv.y);
            }
            if (r1 < M) {
                *(float2*)(outH + (size_t)r1 * 256 + col) = make_float2(c[2], c[3]);
                *(float2*)(outA + (size_t)r1 * 256 + col) =
                    make_float2(c[2] * nr1 + bv.x, c[3] * nr1 + bv.y);
            }
        }
    }
}

// ---------------- edge scatter (atomic f32) ----------------
__global__ void k_scatter(float* __restrict__ outA) {
    int gid = blockIdx.x * blockDim.x + threadIdx.x;
    int e = gid >> 5;
    int lane = gid & 31;
    if (e >= NE) return;
    int s = g_src[e], d = g_dst[e];
    float nrm = g_dinv[s] * g_dinv[d];
    const float4* hs = (const float4*)(g_bufH + (size_t)s * FDIM);
    float* od = outA + (size_t)d * FDIM;
#pragma unroll
    for (int p = 0; p < 2; p++) {
        int c = lane + p * 32;
        float4 v = hs[c];
        atomicAdd(od + c * 4 + 0, v.x * nrm);
        atomicAdd(od + c * 4 + 1, v.y * nrm);
        atomicAdd(od + c * 4 + 2, v.z * nrm);
        atomicAdd(od + c * 4 + 3, v.w * nrm);
    }
}

// ---------------- pooling (ReLU fused) + FC ----------------
__global__ void k_pool_zero() {
    int i = blockIdx.x * blockDim.x + threadIdx.x;
    if (i < NG * FDIM) g_pool[i] = 0.0f;
    if (i < NG) g_cnt[i] = 0.0f;
}

__global__ void k_pool(const float* __restrict__ in) {
    int i = blockIdx.x * blockDim.x + threadIdx.x;
    if (i >= NN * 64) return;
    int node = i >> 6;
    int c = i & 63;
    int g = g_batch[node];
    float4 v = *(const float4*)(in + (size_t)node * FDIM + c * 4);
    float* pp = g_pool + (size_t)g * FDIM + c * 4;
    atomicAdd(pp + 0, fmaxf(v.x, 0.f));
    atomicAdd(pp + 1, fmaxf(v.y, 0.f));
    atomicAdd(pp + 2, fmaxf(v.z, 0.f));
    atomicAdd(pp + 3, fmaxf(v.w, 0.f));
    if (c == 0) atomicAdd(&g_cnt[g], 1.0f);
}

__global__ void k_fc(const float* __restrict__ Wfc, const float* __restrict__ bfc,
                     float* __restrict__ out) {
    __shared__ float sp[FDIM];
    int g = blockIdx.x;
    float inv = 1.0f / fmaxf(g_cnt[g], 1.0f);
    for (int f = threadIdx.x; f < FDIM; f += 128)
        sp[f] = g_pool[(size_t)g * FDIM + f] * inv;
    __syncthreads();
    int j = threadIdx.x;
    float acc = bfc[j];
#pragma unroll 4
    for (int f = 0; f < FDIM; f++) acc += sp[f] * Wfc[(size_t)f * FOUT + j];
    out[(size_t)g * FOUT + j] = acc;
}

// ---------------- launch ----------------
extern "C" void kernel_launch(void* const* d_in, const int* in_sizes, int n_in,
                              void* d_out, int out_size) {
    (void)in_sizes; (void)n_in; (void)out_size;
    const float* x   = (const float*)d_in[0];
    const void*  ei  = d_in[1];
    const void*  bt  = d_in[2];
    const float* W1  = (const float*)d_in[3];
    const float* b1  = (const float*)d_in[4];
    const float* W2  = (const float*)d_in[5];
    const float* b2  = (const float*)d_in[6];
    const float* W3  = (const float*)d_in[7];
    const float* b3  = (const float*)d_in[8];
    const float* Wfc = (const float*)d_in[9];
    const float* bfc = (const float*)d_in[10];
    float* out = (float*)d_out;

    float *buf0 = nullptr, *buf1 = nullptr, *bufH = nullptr;
    cudaGetSymbolAddress((void**)&buf0, g_buf0);
    cudaGetSymbolAddress((void**)&buf1, g_buf1);
    cudaGetSymbolAddress((void**)&bufH, g_bufH);

    cudaFuncSetAttribute(k_gemm, cudaFuncAttributeMaxDynamicSharedMemorySize, GEMM_SMEM);

    // index prep
    k_detect<<<1, 1>>>(ei);
    k_convert<<<(NE + 255) / 256, 256>>>(ei, bt);
    k_deg_init<<<(NN + 255) / 256, 256>>>();
    k_deg_count<<<(NE + 255) / 256, 256>>>();
    k_dinv<<<(NN + 255) / 256, 256>>>();

    dim3 gemm_grid((NN + 127) / 128, 2);
    const int n_scat = (NE * 32 + 255) / 256;

    // layer 1 (K=128): x -> buf0
    k_wsplit<<<(128 * 256 + 255) / 256, 256>>>(W1, 128);
    k_gemm<<<gemm_grid, 256, GEMM_SMEM>>>(x, b1, bufH, buf0, NN, 128, 0);
    k_scatter<<<n_scat, 256>>>(buf0);
    // layer 2 (K=256): buf0 -> buf1
    k_wsplit<<<(256 * 256 + 255) / 256, 256>>>(W2, 256);
    k_gemm<<<gemm_grid, 256, GEMM_SMEM>>>(buf0, b2, bufH, buf1, NN, 256, 1);
    k_scatter<<<n_scat, 256>>>(buf1);
    // layer 3 (K=256): buf1 -> buf0
    k_wsplit<<<(256 * 256 + 255) / 256, 256>>>(W3, 256);
    k_gemm<<<gemm_grid, 256, GEMM_SMEM>>>(buf1, b3, bufH, buf0, NN, 256, 1);
    k_scatter<<<n_scat, 256>>>(buf0);

    // pool + fc
    k_pool_zero<<<(NG * FDIM + 255) / 256, 256>>>();
    k_pool<<<(NN * 64 + 255) / 256, 256>>>(buf0);
    k_fc<<<NG, 128>>>(Wfc, bfc, out);
}

// round 5
// speedup vs baseline: 1.3766x; 1.0812x over previous
#include <cuda_runtime.h>
#include <cuda_bf16.h>
#include <math.h>
#include <stdint.h>

#define NN 100000
#define NE 320000
#define NG 512
#define FDIM 256
#define FOUT 128

// ---------------- scratch (static device memory; no allocation) ----------------
__device__ __align__(16) float g_buf0[(size_t)NN * FDIM];
__device__ __align__(16) float g_buf1[(size_t)NN * FDIM];
__device__ __align__(16) float g_bufH[(size_t)NN * FDIM];
__device__ float g_dinv[NN];
__device__ int   g_src[NE];
__device__ int   g_dst[NE];
__device__ int   g_batch[NN];
__device__ float g_pool[NG * FDIM];
__device__ float g_cnt[NG];
__device__ int   g_flag;
__device__ __align__(16) __nv_bfloat16 g_wt_hi[256 * 256];  // W^T split hi  [N][K]
__device__ __align__(16) __nv_bfloat16 g_wt_lo[256 * 256];  // W^T split lo  [N][K]

// ---------------- helpers ----------------
__device__ __forceinline__ uint32_t smem_u32(const void* p) {
    uint32_t a;
    asm("{ .reg .u64 t; cvta.to.shared.u64 t, %1; cvt.u32.u64 %0, t; }" : "=r"(a) : "l"(p));
    return a;
}
__device__ __forceinline__ void ldmat_x4(uint32_t* r, uint32_t addr) {
    asm volatile("ldmatrix.sync.aligned.m8n8.x4.shared.b16 {%0,%1,%2,%3}, [%4];"
                 : "=r"(r[0]), "=r"(r[1]), "=r"(r[2]), "=r"(r[3]) : "r"(addr));
}
__device__ __forceinline__ void mma16816(float* c, const uint32_t* a, const uint32_t* b) {
    asm volatile("mma.sync.aligned.m16n8k16.row.col.f32.bf16.bf16.f32 "
                 "{%0,%1,%2,%3}, {%4,%5,%6,%7}, {%8,%9}, {%0,%1,%2,%3};"
                 : "+f"(c[0]), "+f"(c[1]), "+f"(c[2]), "+f"(c[3])
                 : "r"(a[0]), "r"(a[1]), "r"(a[2]), "r"(a[3]), "r"(b[0]), "r"(b[1]));
}
__device__ __forceinline__ void cp16(uint32_t smem_addr, const void* gptr) {
    asm volatile("cp.async.cg.shared.global [%0], [%1], 16;" :: "r"(smem_addr), "l"(gptr));
}
#define CP_COMMIT() asm volatile("cp.async.commit_group;" ::: "memory")
#define CP_WAIT(n)  asm volatile("cp.async.wait_group %0;" :: "n"(n) : "memory")
__device__ __forceinline__ void red_v4(float* addr, float a, float b, float c, float d) {
    asm volatile("red.global.add.v4.f32 [%0], {%1,%2,%3,%4};"
                 :: "l"(addr), "f"(a), "f"(b), "f"(c), "f"(d) : "memory");
}

// ---------------- index dtype detection + conversion ----------------
__global__ void k_detect(const void* e) {
    const long long* p = (const long long*)e;
    int is64 = 1;
    for (int i = 0; i < 16; i++) {
        long long v = p[i];
        if (v < 0 || v >= NN) is64 = 0;
    }
    g_flag = is64;
}

__global__ void k_convert(const void* e, const void* b) {
    int i = blockIdx.x * blockDim.x + threadIdx.x;
    int f64 = g_flag;
    if (i < NE) {
        if (f64) {
            const long long* p = (const long long*)e;
            g_src[i] = (int)p[i];
            g_dst[i] = (int)p[NE + i];
        } else {
            const int* p = (const int*)e;
            g_src[i] = p[i];
            g_dst[i] = p[NE + i];
        }
    }
    if (i < NN) {
        if (f64) g_batch[i] = (int)((const long long*)b)[i];
        else     g_batch[i] = ((const int*)b)[i];
    }
}

__global__ void k_deg_init() {
    int i = blockIdx.x * blockDim.x + threadIdx.x;
    if (i < NN) g_dinv[i] = 1.0f;
}
__global__ void k_deg_count() {
    int i = blockIdx.x * blockDim.x + threadIdx.x;
    if (i < NE) atomicAdd(&g_dinv[g_dst[i]], 1.0f);
}
__global__ void k_dinv() {
    int i = blockIdx.x * blockDim.x + threadIdx.x;
    if (i < NN) g_dinv[i] = rsqrtf(g_dinv[i]);
}

// ---------------- weight transpose + bf16 split ----------------
__global__ void k_wsplit(const float* __restrict__ W, int K) {
    int i = blockIdx.x * blockDim.x + threadIdx.x;
    if (i >= K * 256) return;
    int k = i >> 8, n = i & 255;
    float v = W[i];
    __nv_bfloat16 h = __float2bfloat16(v);
    float r = v - __bfloat162float(h);
    g_wt_hi[(size_t)n * K + k] = h;
    g_wt_lo[(size_t)n * K + k] = __float2bfloat16(r);
}

// ---------------- mma.sync split-bf16 GEMM, 128x256 per CTA, cp.async pipelined ---
// A (full K, bf16 hi/lo) resident in smem; B double-buffered per 64-K chunk.
#define TSTR 72                 // B smem row stride (bf16 elems)
#define SB0  135168             // B region offset (A region max = 128*264*2*2)
#define SBUF 36864              // one B buffer (hi+lo)
#define SBLO 18432              // lo offset within B buffer
#define GEMM_SMEM 208896

__global__ void __launch_bounds__(256, 1)
k_gemm(const float* __restrict__ A, const float* __restrict__ bias,
       float* __restrict__ outH, float* __restrict__ outA, int M, int K, int relu)
{
    extern __shared__ char smem[];
    uint32_t sb = smem_u32(smem);
    int tid = threadIdx.x;
    int wid = tid >> 5;
    int lane = tid & 31;
    int bm = blockIdx.x * 128;
    int wm = (wid >> 2) * 64;
    int wn = (wid & 3) * 32;

    const int AST = K + 8;                      // A smem row stride (elems)
    const uint32_t aLoOff = (uint32_t)(128 * AST * 2);
    const int nch = K >> 6;
    const int ntot = 2 * nch;                   // nhalves * chunks

    // ---- issue B prefetch for global chunk 0 (nh=0, ch=0, buf 0) ----
    {
        uint32_t base = sb + SB0;
#pragma unroll
        for (int it = 0; it < 4; it++) {
            int idx = tid + it * 256;
            int row = idx >> 3, g = idx & 7;
            uint32_t off = (uint32_t)(row * TSTR + g * 8) * 2;
            cp16(base + off,        g_wt_hi + (size_t)row * K + g * 8);
            cp16(base + SBLO + off, g_wt_lo + (size_t)row * K + g * 8);
        }
        CP_COMMIT();
    }

    // ---- fill A: 128 rows x K f32 -> bf16 hi/lo (once) ----
    for (int idx = tid; idx < 128 * (K >> 2); idx += 256) {
        int row = idx / (K >> 2);
        int g   = idx % (K >> 2);
        float4 v = make_float4(0.f, 0.f, 0.f, 0.f);
        int gr = bm + row;
        if (gr < M) v = *(const float4*)(A + (size_t)gr * K + g * 4);
        if (relu) {
            v.x = fmaxf(v.x, 0.f); v.y = fmaxf(v.y, 0.f);
            v.z = fmaxf(v.z, 0.f); v.w = fmaxf(v.w, 0.f);
        }
        __nv_bfloat16 h0 = __float2bfloat16(v.x), h1 = __float2bfloat16(v.y);
        __nv_bfloat16 h2 = __float2bfloat16(v.z), h3 = __float2bfloat16(v.w);
        __nv_bfloat16 l0 = __float2bfloat16(v.x - __bfloat162float(h0));
        __nv_bfloat16 l1 = __float2bfloat16(v.y - __bfloat162float(h1));
        __nv_bfloat16 l2 = __float2bfloat16(v.z - __bfloat162float(h2));
        __nv_bfloat16 l3 = __float2bfloat16(v.w - __bfloat162float(h3));
        uint2 hp, lp;
        hp.x = ((uint32_t)__bfloat16_as_ushort(h1) << 16) | __bfloat16_as_ushort(h0);
        hp.y = ((uint32_t)__bfloat16_as_ushort(h3) << 16) | __bfloat16_as_ushort(h2);
        lp.x = ((uint32_t)__bfloat16_as_ushort(l1) << 16) | __bfloat16_as_ushort(l0);
        lp.y = ((uint32_t)__bfloat16_as_ushort(l3) << 16) | __bfloat16_as_ushort(l2);
        uint32_t off = (uint32_t)(row * AST + g * 4) * 2;
        *(uint2*)(smem + off)          = hp;
        *(uint2*)(smem + aLoOff + off) = lp;
    }

    float acc[4][4][4];
#pragma unroll
    for (int mi = 0; mi < 4; mi++)
#pragma unroll
        for (int ni = 0; ni < 4; ni++)
#pragma unroll
            for (int q = 0; q < 4; q++) acc[mi][ni][q] = 0.0f;

    for (int t = 0; t < ntot; t++) {
        int nh = t / nch, ch = t % nch;

        // prefetch next global chunk
        if (t + 1 < ntot) {
            int nh2 = (t + 1) / nch, ch2 = (t + 1) % nch;
            int n0b = nh2 * 128, k0b = ch2 * 64;
            uint32_t base = sb + SB0 + ((t + 1) & 1) * SBUF;
#pragma unroll
            for (int it = 0; it < 4; it++) {
                int idx = tid + it * 256;
                int row = idx >> 3, g = idx & 7;
                uint32_t off = (uint32_t)(row * TSTR + g * 8) * 2;
                const size_t gsrc = (size_t)(n0b + row) * K + k0b + g * 8;
                cp16(base + off,        g_wt_hi + gsrc);
                cp16(base + SBLO + off, g_wt_lo + gsrc);
            }
            CP_COMMIT();
            CP_WAIT(1);
        } else {
            CP_WAIT(0);
        }
        __syncthreads();

        // ---- MMA on buffer t&1, A columns [ch*64, ch*64+64) ----
        uint32_t bBase = sb + SB0 + (t & 1) * SBUF;
        int k0 = ch * 64;
#pragma unroll
        for (int ks = 0; ks < 4; ks++) {
            int kk = k0 + ks * 16;
            uint32_t ah[4][4], al[4][4], bh[2][4], bl[2][4];
            int arow = (lane & 15);
            int acol = kk + ((lane >> 4) << 3);
#pragma unroll
            for (int mi = 0; mi < 4; mi++) {
                uint32_t off = (uint32_t)((wm + mi * 16 + arow) * AST + acol) * 2;
                ldmat_x4(ah[mi], sb + off);
                ldmat_x4(al[mi], sb + aLoOff + off);
            }
            int brow = ((lane >> 4) << 3) + (lane & 7);
            int bcol = ks * 16 + ((lane >> 3) & 1) * 8;
#pragma unroll
            for (int j = 0; j < 2; j++) {
                uint32_t off = (uint32_t)((wn + 16 * j + brow) * TSTR + bcol) * 2;
                ldmat_x4(bh[j], bBase + off);
                ldmat_x4(bl[j], bBase + SBLO + off);
            }
#pragma unroll
            for (int mi = 0; mi < 4; mi++) {
#pragma unroll
                for (int ni = 0; ni < 4; ni++) {
                    const uint32_t* bhp = &bh[ni >> 1][(ni & 1) * 2];
                    const uint32_t* blp = &bl[ni >> 1][(ni & 1) * 2];
                    mma16816(acc[mi][ni], ah[mi], bhp);
                    mma16816(acc[mi][ni], ah[mi], blp);
                    mma16816(acc[mi][ni], al[mi], bhp);
                }
            }
        }

        // ---- end of this n-half: epilogue + acc reset ----
        if (ch == nch - 1) {
            int n0 = nh * 128;
            int g = lane >> 2, tg = lane & 3;
#pragma unroll
            for (int mi = 0; mi < 4; mi++) {
                int r0 = bm + wm + mi * 16 + g;
                int r1 = r0 + 8;
                float nr0 = 0.f, nr1 = 0.f;
                if (r0 < M) { nr0 = g_dinv[r0]; nr0 *= nr0; }
                if (r1 < M) { nr1 = g_dinv[r1]; nr1 *= nr1; }
#pragma unroll
                for (int ni = 0; ni < 4; ni++) {
                    int col = n0 + wn + ni * 8 + tg * 2;
                    float2 bv = *(const float2*)(bias + col);
                    float* c = acc[mi][ni];
                    if (r0 < M) {
                        *(float2*)(outH + (size_t)r0 * 256 + col) = make_float2(c[0], c[1]);
                        *(float2*)(outA + (size_t)r0 * 256 + col) =
                            make_float2(c[0] * nr0 + bv.x, c[1] * nr0 + bv.y);
                    }
                    if (r1 < M) {
                        *(float2*)(outH + (size_t)r1 * 256 + col) = make_float2(c[2], c[3]);
                        *(float2*)(outA + (size_t)r1 * 256 + col) =
                            make_float2(c[2] * nr1 + bv.x, c[3] * nr1 + bv.y);
                    }
                    c[0] = c[1] = c[2] = c[3] = 0.f;
                }
            }
        }
        __syncthreads();
    }
}

// ---------------- edge scatter (vector red) ----------------
__global__ void k_scatter(float* __restrict__ outA) {
    int gid = blockIdx.x * blockDim.x + threadIdx.x;
    int e = gid >> 5;
    int lane = gid & 31;
    if (e >= NE) return;
    int s = g_src[e], d = g_dst[e];
    float nrm = g_dinv[s] * g_dinv[d];
    const float4* hs = (const float4*)(g_bufH + (size_t)s * FDIM);
    float* od = outA + (size_t)d * FDIM;
#pragma unroll
    for (int p = 0; p < 2; p++) {
        int c = lane + p * 32;
        float4 v = hs[c];
        red_v4(od + c * 4, v.x * nrm, v.y * nrm, v.z * nrm, v.w * nrm);
    }
}

// ---------------- pooling (ReLU fused) + FC ----------------
__global__ void k_pool_zero() {
    int i = blockIdx.x * blockDim.x + threadIdx.x;
    if (i < NG * FDIM) g_pool[i] = 0.0f;
    if (i < NG) g_cnt[i] = 0.0f;
}

__global__ void k_pool(const float* __restrict__ in) {
    int i = blockIdx.x * blockDim.x + threadIdx.x;
    if (i >= NN * 64) return;
    int node = i >> 6;
    int c = i & 63;
    int g = g_batch[node];
    float4 v = *(const float4*)(in + (size_t)node * FDIM + c * 4);
    red_v4(g_pool + (size_t)g * FDIM + c * 4,
           fmaxf(v.x, 0.f), fmaxf(v.y, 0.f), fmaxf(v.z, 0.f), fmaxf(v.w, 0.f));
    if (c == 0) atomicAdd(&g_cnt[g], 1.0f);
}

__global__ void k_fc(const float* __restrict__ Wfc, const float* __restrict__ bfc,
                     float* __restrict__ out) {
    __shared__ float sp[FDIM];
    int g = blockIdx.x;
    float inv = 1.0f / fmaxf(g_cnt[g], 1.0f);
    for (int f = threadIdx.x; f < FDIM; f += 128)
        sp[f] = g_pool[(size_t)g * FDIM + f] * inv;
    __syncthreads();
    int j = threadIdx.x;
    float acc = bfc[j];
#pragma unroll 4
    for (int f = 0; f < FDIM; f++) acc += sp[f] * Wfc[(size_t)f * FOUT + j];
    out[(size_t)g * FOUT + j] = acc;
}

// ---------------- launch ----------------
extern "C" void kernel_launch(void* const* d_in, const int* in_sizes, int n_in,
                              void* d_out, int out_size) {
    (void)in_sizes; (void)n_in; (void)out_size;
    const float* x   = (const float*)d_in[0];
    const void*  ei  = d_in[1];
    const void*  bt  = d_in[2];
    const float* W1  = (const float*)d_in[3];
    const float* b1  = (const float*)d_in[4];
    const float* W2  = (const float*)d_in[5];
    const float* b2  = (const float*)d_in[6];
    const float* W3  = (const float*)d_in[7];
    const float* b3  = (const float*)d_in[8];
    const float* Wfc = (const float*)d_in[9];
    const float* bfc = (const float*)d_in[10];
    float* out = (float*)d_out;

    float *buf0 = nullptr, *buf1 = nullptr, *bufH = nullptr;
    cudaGetSymbolAddress((void**)&buf0, g_buf0);
    cudaGetSymbolAddress((void**)&buf1, g_buf1);
    cudaGetSymbolAddress((void**)&bufH, g_bufH);

    cudaFuncSetAttribute(k_gemm, cudaFuncAttributeMaxDynamicSharedMemorySize, GEMM_SMEM);

    // index prep
    k_detect<<<1, 1>>>(ei);
    k_convert<<<(NE + 255) / 256, 256>>>(ei, bt);
    k_deg_init<<<(NN + 255) / 256, 256>>>();
    k_deg_count<<<(NE + 255) / 256, 256>>>();
    k_dinv<<<(NN + 255) / 256, 256>>>();

    const int gemm_grid = (NN + 127) / 128;   // 782
    const int n_scat = (NE * 32 + 255) / 256;

    // layer 1 (K=128): x -> buf0
    k_wsplit<<<(128 * 256 + 255) / 256, 256>>>(W1, 128);
    k_gemm<<<gemm_grid, 256, GEMM_SMEM>>>(x, b1, bufH, buf0, NN, 128, 0);
    k_scatter<<<n_scat, 256>>>(buf0);
    // layer 2 (K=256): buf0 -> buf1
    k_wsplit<<<(256 * 256 + 255) / 256, 256>>>(W2, 256);
    k_gemm<<<gemm_grid, 256, GEMM_SMEM>>>(buf0, b2, bufH, buf1, NN, 256, 1);
    k_scatter<<<n_scat, 256>>>(buf1);
    // layer 3 (K=256): buf1 -> buf0
    k_wsplit<<<(256 * 256 + 255) / 256, 256>>>(W3, 256);
    k_gemm<<<gemm_grid, 256, GEMM_SMEM>>>(buf1, b3, bufH, buf0, NN, 256, 1);
    k_scatter<<<n_scat, 256>>>(buf0);

    // pool + fc
    k_pool_zero<<<(NG * FDIM + 255) / 256, 256>>>();
    k_pool<<<(NN * 64 + 255) / 256, 256>>>(buf0);
    k_fc<<<NG, 128>>>(Wfc, bfc, out);
}

// round 6
// speedup vs baseline: 1.9753x; 1.4349x over previous
#include <cuda_runtime.h>
#include <cuda_bf16.h>
#include <math.h>
#include <stdint.h>

#define NN 100000
#define NE 320000
#define NG 512
#define FDIM 256
#define FOUT 128
#define NBLK 391   // ceil(NN/256)

// ---------------- scratch (static device memory; no allocation) ----------------
__device__ __align__(16) float g_buf0[(size_t)NN * FDIM];
__device__ __align__(16) float g_buf1[(size_t)NN * FDIM];
__device__ __align__(16) float g_bufH[(size_t)NN * FDIM];
__device__ float g_dinv[NN];
__device__ int   g_deg[NN];
__device__ int   g_rowptr[NN];
__device__ int   g_cursor[NN];
__device__ int   g_blksum[512];
__device__ int   g_blkoff[512];
__device__ int   g_csrc[NE];
__device__ float g_cnrm[NE];
__device__ int   g_src[NE];
__device__ int   g_dst[NE];
__device__ int   g_batch[NN];
__device__ float g_pool[NG * FDIM];
__device__ int   g_flag;
__device__ __align__(16) __nv_bfloat16 g_wt_hi[256 * 256];  // W^T split hi [N][K]
__device__ __align__(16) __nv_bfloat16 g_wt_lo[256 * 256];  // W^T split lo [N][K]

// ---------------- helpers ----------------
__device__ __forceinline__ uint32_t smem_u32(const void* p) {
    uint32_t a;
    asm("{ .reg .u64 t; cvta.to.shared.u64 t, %1; cvt.u32.u64 %0, t; }" : "=r"(a) : "l"(p));
    return a;
}
__device__ __forceinline__ void ldmat_x4(uint32_t* r, uint32_t addr) {
    asm volatile("ldmatrix.sync.aligned.m8n8.x4.shared.b16 {%0,%1,%2,%3}, [%4];"
                 : "=r"(r[0]), "=r"(r[1]), "=r"(r[2]), "=r"(r[3]) : "r"(addr));
}
__device__ __forceinline__ void mma16816(float* c, const uint32_t* a, const uint32_t* b) {
    asm volatile("mma.sync.aligned.m16n8k16.row.col.f32.bf16.bf16.f32 "
                 "{%0,%1,%2,%3}, {%4,%5,%6,%7}, {%8,%9}, {%0,%1,%2,%3};"
                 : "+f"(c[0]), "+f"(c[1]), "+f"(c[2]), "+f"(c[3])
                 : "r"(a[0]), "r"(a[1]), "r"(a[2]), "r"(a[3]), "r"(b[0]), "r"(b[1]));
}
__device__ __forceinline__ void cp16(uint32_t smem_addr, const void* gptr) {
    asm volatile("cp.async.cg.shared.global [%0], [%1], 16;" :: "r"(smem_addr), "l"(gptr));
}
#define CP_COMMIT() asm volatile("cp.async.commit_group;" ::: "memory")
#define CP_WAIT(n)  asm volatile("cp.async.wait_group %0;" :: "n"(n) : "memory")

// ---------------- index dtype detection + conversion ----------------
__global__ void k_detect(const void* e) {
    const long long* p = (const long long*)e;
    int is64 = 1;
    for (int i = 0; i < 16; i++) {
        long long v = p[i];
        if (v < 0 || v >= NN) is64 = 0;
    }
    g_flag = is64;
}

__global__ void k_convert(const void* e, const void* b) {
    int i = blockIdx.x * blockDim.x + threadIdx.x;
    int f64 = g_flag;
    if (i < NE) {
        if (f64) {
            const long long* p = (const long long*)e;
            g_src[i] = (int)p[i];
            g_dst[i] = (int)p[NE + i];
        } else {
            const int* p = (const int*)e;
            g_src[i] = p[i];
            g_dst[i] = p[NE + i];
        }
    }
    if (i < NN) {
        if (f64) g_batch[i] = (int)((const long long*)b)[i];
        else     g_batch[i] = ((const int*)b)[i];
        g_deg[i] = 0;
    }
}

__global__ void k_deg_count() {
    int i = blockIdx.x * blockDim.x + threadIdx.x;
    if (i < NE) atomicAdd(&g_deg[g_dst[i]], 1);
}
__global__ void k_dinv() {
    int i = blockIdx.x * blockDim.x + threadIdx.x;
    if (i < NN) g_dinv[i] = rsqrtf((float)g_deg[i] + 1.0f);
}

// ---------------- CSR build: 2-level exclusive scan + fill ----------------
__global__ void k_scan1() {
    __shared__ int s[256];
    int tid = threadIdx.x;
    int i = blockIdx.x * 256 + tid;
    int v = (i < NN) ? g_deg[i] : 0;
    s[tid] = v;
#pragma unroll
    for (int off = 1; off < 256; off <<= 1) {
        __syncthreads();
        int t = (tid >= off) ? s[tid - off] : 0;
        __syncthreads();
        s[tid] += t;
    }
    __syncthreads();
    if (i < NN) g_rowptr[i] = s[tid] - v;
    if (tid == 255) g_blksum[blockIdx.x] = s[255];
}
__global__ void k_scan2() {
    __shared__ int s[512];
    int tid = threadIdx.x;
    int v = (tid < NBLK) ? g_blksum[tid] : 0;
    s[tid] = v;
#pragma unroll
    for (int off = 1; off < 512; off <<= 1) {
        __syncthreads();
        int t = (tid >= off) ? s[tid - off] : 0;
        __syncthreads();
        s[tid] += t;
    }
    __syncthreads();
    g_blkoff[tid] = s[tid] - v;
}
__global__ void k_scan3() {
    int i = blockIdx.x * blockDim.x + threadIdx.x;
    if (i < NN) {
        g_rowptr[i] += g_blkoff[blockIdx.x * 256 / 256 == 0 ? 0 : 0]; // placeholder (fixed below)
    }
}
// (note: correct version defined here)
__global__ void k_scan3b() {
    int i = blockIdx.x * 256 + threadIdx.x;
    if (i < NN) {
        g_rowptr[i] += g_blkoff[blockIdx.x];
        g_cursor[i] = 0;
    }
}
__global__ void k_csrfill() {
    int e = blockIdx.x * blockDim.x + threadIdx.x;
    if (e >= NE) return;
    int s = g_src[e], d = g_dst[e];
    int pos = atomicAdd(&g_cursor[d], 1);
    int slot = g_rowptr[d] + pos;
    g_csrc[slot] = s;
    g_cnrm[slot] = g_dinv[s] * g_dinv[d];
}

// ---------------- weight transpose + bf16 split ----------------
__global__ void k_wsplit(const float* __restrict__ W, int K) {
    int i = blockIdx.x * blockDim.x + threadIdx.x;
    if (i >= K * 256) return;
    int k = i >> 8, n = i & 255;
    float v = W[i];
    __nv_bfloat16 h = __float2bfloat16(v);
    float r = v - __bfloat162float(h);
    g_wt_hi[(size_t)n * K + k] = h;
    g_wt_lo[(size_t)n * K + k] = __float2bfloat16(r);
}

// ---------------- mma.sync split-bf16 GEMM (unchanged from R5) ----------------
#define TSTR 72
#define SB0  135168
#define SBUF 36864
#define SBLO 18432
#define GEMM_SMEM 208896

__global__ void __launch_bounds__(256, 1)
k_gemm(const float* __restrict__ A, const float* __restrict__ bias,
       float* __restrict__ outH, float* __restrict__ outA, int M, int K, int relu)
{
    extern __shared__ char smem[];
    uint32_t sb = smem_u32(smem);
    int tid = threadIdx.x;
    int wid = tid >> 5;
    int lane = tid & 31;
    int bm = blockIdx.x * 128;
    int wm = (wid >> 2) * 64;
    int wn = (wid & 3) * 32;

    const int AST = K + 8;
    const uint32_t aLoOff = (uint32_t)(128 * AST * 2);
    const int nch = K >> 6;
    const int ntot = 2 * nch;

    {
        uint32_t base = sb + SB0;
#pragma unroll
        for (int it = 0; it < 4; it++) {
            int idx = tid + it * 256;
            int row = idx >> 3, g = idx & 7;
            uint32_t off = (uint32_t)(row * TSTR + g * 8) * 2;
            cp16(base + off,        g_wt_hi + (size_t)row * K + g * 8);
            cp16(base + SBLO + off, g_wt_lo + (size_t)row * K + g * 8);
        }
        CP_COMMIT();
    }

    for (int idx = tid; idx < 128 * (K >> 2); idx += 256) {
        int row = idx / (K >> 2);
        int g   = idx % (K >> 2);
        float4 v = make_float4(0.f, 0.f, 0.f, 0.f);
        int gr = bm + row;
        if (gr < M) v = *(const float4*)(A + (size_t)gr * K + g * 4);
        if (relu) {
            v.x = fmaxf(v.x, 0.f); v.y = fmaxf(v.y, 0.f);
            v.z = fmaxf(v.z, 0.f); v.w = fmaxf(v.w, 0.f);
        }
        __nv_bfloat16 h0 = __float2bfloat16(v.x), h1 = __float2bfloat16(v.y);
        __nv_bfloat16 h2 = __float2bfloat16(v.z), h3 = __float2bfloat16(v.w);
        __nv_bfloat16 l0 = __float2bfloat16(v.x - __bfloat162float(h0));
        __nv_bfloat16 l1 = __float2bfloat16(v.y - __bfloat162float(h1));
        __nv_bfloat16 l2 = __float2bfloat16(v.z - __bfloat162float(h2));
        __nv_bfloat16 l3 = __float2bfloat16(v.w - __bfloat162float(h3));
        uint2 hp, lp;
        hp.x = ((uint32_t)__bfloat16_as_ushort(h1) << 16) | __bfloat16_as_ushort(h0);
        hp.y = ((uint32_t)__bfloat16_as_ushort(h3) << 16) | __bfloat16_as_ushort(h2);
        lp.x = ((uint32_t)__bfloat16_as_ushort(l1) << 16) | __bfloat16_as_ushort(l0);
        lp.y = ((uint32_t)__bfloat16_as_ushort(l3) << 16) | __bfloat16_as_ushort(l2);
        uint32_t off = (uint32_t)(row * AST + g * 4) * 2;
        *(uint2*)(smem + off)          = hp;
        *(uint2*)(smem + aLoOff + off) = lp;
    }

    float acc[4][4][4];
#pragma unroll
    for (int mi = 0; mi < 4; mi++)
#pragma unroll
        for (int ni = 0; ni < 4; ni++)
#pragma unroll
            for (int q = 0; q < 4; q++) acc[mi][ni][q] = 0.0f;

    for (int t = 0; t < ntot; t++) {
        int nh = t / nch, ch = t % nch;

        if (t + 1 < ntot) {
            int nh2 = (t + 1) / nch, ch2 = (t + 1) % nch;
            int n0b = nh2 * 128, k0b = ch2 * 64;
            uint32_t base = sb + SB0 + ((t + 1) & 1) * SBUF;
#pragma unroll
            for (int it = 0; it < 4; it++) {
                int idx = tid + it * 256;
                int row = idx >> 3, g = idx & 7;
                uint32_t off = (uint32_t)(row * TSTR + g * 8) * 2;
                const size_t gsrc = (size_t)(n0b + row) * K + k0b + g * 8;
                cp16(base + off,        g_wt_hi + gsrc);
                cp16(base + SBLO + off, g_wt_lo + gsrc);
            }
            CP_COMMIT();
            CP_WAIT(1);
        } else {
            CP_WAIT(0);
        }
        __syncthreads();

        uint32_t bBase = sb + SB0 + (t & 1) * SBUF;
        int k0 = ch * 64;
#pragma unroll
        for (int ks = 0; ks < 4; ks++) {
            int kk = k0 + ks * 16;
            uint32_t ah[4][4], al[4][4], bh[2][4], bl[2][4];
            int arow = (lane & 15);
            int acol = kk + ((lane >> 4) << 3);
#pragma unroll
            for (int mi = 0; mi < 4; mi++) {
                uint32_t off = (uint32_t)((wm + mi * 16 + arow) * AST + acol) * 2;
                ldmat_x4(ah[mi], sb + off);
                ldmat_x4(al[mi], sb + aLoOff + off);
            }
            int brow = ((lane >> 4) << 3) + (lane & 7);
            int bcol = ks * 16 + ((lane >> 3) & 1) * 8;
#pragma unroll
            for (int j = 0; j < 2; j++) {
                uint32_t off = (uint32_t)((wn + 16 * j + brow) * TSTR + bcol) * 2;
                ldmat_x4(bh[j], bBase + off);
                ldmat_x4(bl[j], bBase + SBLO + off);
            }
#pragma unroll
            for (int mi = 0; mi < 4; mi++) {
#pragma unroll
                for (int ni = 0; ni < 4; ni++) {
                    const uint32_t* bhp = &bh[ni >> 1][(ni & 1) * 2];
                    const uint32_t* blp = &bl[ni >> 1][(ni & 1) * 2];
                    mma16816(acc[mi][ni], ah[mi], bhp);
                    mma16816(acc[mi][ni], ah[mi], blp);
                    mma16816(acc[mi][ni], al[mi], bhp);
                }
            }
        }

        if (ch == nch - 1) {
            int n0 = nh * 128;
            int g = lane >> 2, tg = lane & 3;
#pragma unroll
            for (int mi = 0; mi < 4; mi++) {
                int r0 = bm + wm + mi * 16 + g;
                int r1 = r0 + 8;
                float nr0 = 0.f, nr1 = 0.f;
                if (r0 < M) { nr0 = g_dinv[r0]; nr0 *= nr0; }
                if (r1 < M) { nr1 = g_dinv[r1]; nr1 *= nr1; }
#pragma unroll
                for (int ni = 0; ni < 4; ni++) {
                    int col = n0 + wn + ni * 8 + tg * 2;
                    float2 bv = *(const float2*)(bias + col);
                    float* c = acc[mi][ni];
                    if (r0 < M) {
                        *(float2*)(outH + (size_t)r0 * 256 + col) = make_float2(c[0], c[1]);
                        *(float2*)(outA + (size_t)r0 * 256 + col) =
                            make_float2(c[0] * nr0 + bv.x, c[1] * nr0 + bv.y);
                    }
                    if (r1 < M) {
                        *(float2*)(outH + (size_t)r1 * 256 + col) = make_float2(c[2], c[3]);
                        *(float2*)(outA + (size_t)r1 * 256 + col) =
                            make_float2(c[2] * nr1 + bv.x, c[3] * nr1 + bv.y);
                    }
                    c[0] = c[1] = c[2] = c[3] = 0.f;
                }
            }
        }
        __syncthreads();
    }
}

// ---------------- CSR gather aggregation: 1 warp per dst node, no atomics -------
__global__ void __launch_bounds__(256) k_gather(float* __restrict__ outA) {
    int node = blockIdx.x * 8 + (threadIdx.x >> 5);
    int lane = threadIdx.x & 31;
    if (node >= NN) return;
    int beg = g_rowptr[node];
    int dg  = g_deg[node];
    float4* row = (float4*)(outA + (size_t)node * FDIM);
    float4 a0 = row[lane];
    float4 a1 = row[lane + 32];
    for (int j = 0; j < dg; j++) {
        int s = __ldg(&g_csrc[beg + j]);
        float nrm = __ldg(&g_cnrm[beg + j]);
        const float4* hs = (const float4*)(g_bufH + (size_t)s * FDIM);
        float4 v0 = hs[lane];
        float4 v1 = hs[lane + 32];
        a0.x += v0.x * nrm; a0.y += v0.y * nrm; a0.z += v0.z * nrm; a0.w += v0.w * nrm;
        a1.x += v1.x * nrm; a1.y += v1.y * nrm; a1.z += v1.z * nrm; a1.w += v1.w * nrm;
    }
    row[lane]      = a0;
    row[lane + 32] = a1;
}

// ---------------- segment pooling (batch sorted) + FC ----------------
__device__ __forceinline__ int lbound(const int* a, int n, int key) {
    int lo = 0, hi = n;
    while (lo < hi) { int m = (lo + hi) >> 1; if (a[m] < key) lo = m + 1; else hi = m; }
    return lo;
}

__global__ void k_pool(const float* __restrict__ in) {
    __shared__ int bnd[2];
    int g = blockIdx.x;
    int t = threadIdx.x;
    if (t == 0) bnd[0] = lbound(g_batch, NN, g);
    if (t == 1) bnd[1] = lbound(g_batch, NN, g + 1);
    __syncthreads();
    int lo = bnd[0], hi = bnd[1];
    float acc = 0.f;
    for (int n = lo; n < hi; n++)
        acc += fmaxf(in[(size_t)n * FDIM + t], 0.f);
    int cnt = hi - lo;
    g_pool[(size_t)g * FDIM + t] = cnt > 0 ? acc / (float)cnt : 0.f;
}

__global__ void k_fc(const float* __restrict__ Wfc, const float* __restrict__ bfc,
                     float* __restrict__ out) {
    __shared__ float sp[FDIM];
    int g = blockIdx.x;
    for (int f = threadIdx.x; f < FDIM; f += 128)
        sp[f] = g_pool[(size_t)g * FDIM + f];
    __syncthreads();
    int j = threadIdx.x;
    float acc = bfc[j];
#pragma unroll 4
    for (int f = 0; f < FDIM; f++) acc += sp[f] * Wfc[(size_t)f * FOUT + j];
    out[(size_t)g * FOUT + j] = acc;
}

// ---------------- launch ----------------
extern "C" void kernel_launch(void* const* d_in, const int* in_sizes, int n_in,
                              void* d_out, int out_size) {
    (void)in_sizes; (void)n_in; (void)out_size;
    const float* x   = (const float*)d_in[0];
    const void*  ei  = d_in[1];
    const void*  bt  = d_in[2];
    const float* W1  = (const float*)d_in[3];
    const float* b1  = (const float*)d_in[4];
    const float* W2  = (const float*)d_in[5];
    const float* b2  = (const float*)d_in[6];
    const float* W3  = (const float*)d_in[7];
    const float* b3  = (const float*)d_in[8];
    const float* Wfc = (const float*)d_in[9];
    const float* bfc = (const float*)d_in[10];
    float* out = (float*)d_out;

    float *buf0 = nullptr, *buf1 = nullptr, *bufH = nullptr;
    cudaGetSymbolAddress((void**)&buf0, g_buf0);
    cudaGetSymbolAddress((void**)&buf1, g_buf1);
    cudaGetSymbolAddress((void**)&bufH, g_bufH);

    cudaFuncSetAttribute(k_gemm, cudaFuncAttributeMaxDynamicSharedMemorySize, GEMM_SMEM);

    // index prep + CSR build
    k_detect<<<1, 1>>>(ei);
    k_convert<<<(NE + 255) / 256, 256>>>(ei, bt);
    k_deg_count<<<(NE + 255) / 256, 256>>>();
    k_dinv<<<(NN + 255) / 256, 256>>>();
    k_scan1<<<NBLK, 256>>>();
    k_scan2<<<1, 512>>>();
    k_scan3b<<<NBLK, 256>>>();
    k_csrfill<<<(NE + 255) / 256, 256>>>();

    const int gemm_grid = (NN + 127) / 128;
    const int gat_grid  = (NN + 7) / 8;

    // layer 1 (K=128): x -> buf0
    k_wsplit<<<(128 * 256 + 255) / 256, 256>>>(W1, 128);
    k_gemm<<<gemm_grid, 256, GEMM_SMEM>>>(x, b1, bufH, buf0, NN, 128, 0);
    k_gather<<<gat_grid, 256>>>(buf0);
    // layer 2 (K=256): buf0 -> buf1
    k_wsplit<<<(256 * 256 + 255) / 256, 256>>>(W2, 256);
    k_gemm<<<gemm_grid, 256, GEMM_SMEM>>>(buf0, b2, bufH, buf1, NN, 256, 1);
    k_gather<<<gat_grid, 256>>>(buf1);
    // layer 3 (K=256): buf1 -> buf0
    k_wsplit<<<(256 * 256 + 255) / 256, 256>>>(W3, 256);
    k_gemm<<<gemm_grid, 256, GEMM_SMEM>>>(buf1, b3, bufH, buf0, NN, 256, 1);
    k_gather<<<gat_grid, 256>>>(buf0);

    // pool + fc
    k_pool<<<NG, FDIM>>>(buf0);
    k_fc<<<NG, 128>>>(Wfc, bfc, out);
}

// round 7
// speedup vs baseline: 2.1995x; 1.1135x over previous
#include <cuda_runtime.h>
#include <cuda_bf16.h>
#include <math.h>
#include <stdint.h>

#define NN 100000
#define NE 320000
#define NG 512
#define FDIM 256
#define FOUT 128
#define NBLK 391   // ceil(NN/256)

// ---------------- scratch (static device memory; no allocation) ----------------
__device__ __align__(16) float g_buf0[(size_t)NN * FDIM];
__device__ __align__(16) float g_buf1[(size_t)NN * FDIM];
__device__ __align__(16) float g_bufH[(size_t)NN * FDIM];
__device__ float g_dinv[NN];
__device__ int   g_deg[NN];
__device__ int   g_rowptr[NN];
__device__ int   g_cursor[NN];
__device__ int   g_blksum[512];
__device__ int   g_blkoff[512];
__device__ int   g_csrc[NE];
__device__ float g_cnrm[NE];
__device__ int   g_src[NE];
__device__ int   g_dst[NE];
__device__ int   g_batch[NN];
__device__ float g_pool[NG * FDIM];
__device__ __align__(16) __nv_bfloat16 g_w1hi[128 * 256];
__device__ __align__(16) __nv_bfloat16 g_w1lo[128 * 256];
__device__ __align__(16) __nv_bfloat16 g_w2hi[256 * 256];
__device__ __align__(16) __nv_bfloat16 g_w2lo[256 * 256];
__device__ __align__(16) __nv_bfloat16 g_w3hi[256 * 256];
__device__ __align__(16) __nv_bfloat16 g_w3lo[256 * 256];

// ---------------- helpers ----------------
__device__ __forceinline__ uint32_t smem_u32(const void* p) {
    uint32_t a;
    asm("{ .reg .u64 t; cvta.to.shared.u64 t, %1; cvt.u32.u64 %0, t; }" : "=r"(a) : "l"(p));
    return a;
}
__device__ __forceinline__ void ldmat_x4(uint32_t* r, uint32_t addr) {
    asm volatile("ldmatrix.sync.aligned.m8n8.x4.shared.b16 {%0,%1,%2,%3}, [%4];"
                 : "=r"(r[0]), "=r"(r[1]), "=r"(r[2]), "=r"(r[3]) : "r"(addr));
}
__device__ __forceinline__ void mma16816(float* c, const uint32_t* a, const uint32_t* b) {
    asm volatile("mma.sync.aligned.m16n8k16.row.col.f32.bf16.bf16.f32 "
                 "{%0,%1,%2,%3}, {%4,%5,%6,%7}, {%8,%9}, {%0,%1,%2,%3};"
                 : "+f"(c[0]), "+f"(c[1]), "+f"(c[2]), "+f"(c[3])
                 : "r"(a[0]), "r"(a[1]), "r"(a[2]), "r"(a[3]), "r"(b[0]), "r"(b[1]));
}
__device__ __forceinline__ void cp16(uint32_t smem_addr, const void* gptr) {
    asm volatile("cp.async.cg.shared.global [%0], [%1], 16;" :: "r"(smem_addr), "l"(gptr));
}
#define CP_COMMIT() asm volatile("cp.async.commit_group;" ::: "memory")
#define CP_WAIT(n)  asm volatile("cp.async.wait_group %0;" :: "n"(n) : "memory")

// ---------------- prep: zero, convert+detect+degree ----------------
__global__ void k_zero() {
    int i = blockIdx.x * blockDim.x + threadIdx.x;
    if (i < NN) g_deg[i] = 0;
}

__global__ void k_prep(const void* e, const void* b) {
    __shared__ int s64;
    if (threadIdx.x == 0) {
        const long long* p = (const long long*)e;
        int is64 = 1;
        for (int t = 0; t < 16; t++) {
            long long v = p[t];
            if (v < 0 || v >= NN) is64 = 0;
        }
        s64 = is64;
    }
    __syncthreads();
    int f64 = s64;
    int i = blockIdx.x * blockDim.x + threadIdx.x;
    if (i < NE) {
        int s, d;
        if (f64) {
            const long long* p = (const long long*)e;
            s = (int)p[i]; d = (int)p[NE + i];
        } else {
            const int* p = (const int*)e;
            s = p[i]; d = p[NE + i];
        }
        g_src[i] = s;
        g_dst[i] = d;
        atomicAdd(&g_deg[d], 1);
    }
    if (i < NN) {
        if (f64) g_batch[i] = (int)((const long long*)b)[i];
        else     g_batch[i] = ((const int*)b)[i];
    }
}

// ---------------- CSR build: 2-level exclusive scan + fill ----------------
__global__ void k_scan1() {
    __shared__ int s[256];
    int tid = threadIdx.x;
    int i = blockIdx.x * 256 + tid;
    int v = (i < NN) ? g_deg[i] : 0;
    s[tid] = v;
#pragma unroll
    for (int off = 1; off < 256; off <<= 1) {
        __syncthreads();
        int t = (tid >= off) ? s[tid - off] : 0;
        __syncthreads();
        s[tid] += t;
    }
    __syncthreads();
    if (i < NN) g_rowptr[i] = s[tid] - v;
    if (tid == 255) g_blksum[blockIdx.x] = s[255];
}
__global__ void k_scan2() {
    __shared__ int s[512];
    int tid = threadIdx.x;
    int v = (tid < NBLK) ? g_blksum[tid] : 0;
    s[tid] = v;
#pragma unroll
    for (int off = 1; off < 512; off <<= 1) {
        __syncthreads();
        int t = (tid >= off) ? s[tid - off] : 0;
        __syncthreads();
        s[tid] += t;
    }
    __syncthreads();
    g_blkoff[tid] = s[tid] - v;
}
__global__ void k_scan3() {
    int i = blockIdx.x * 256 + threadIdx.x;
    if (i < NN) {
        g_rowptr[i] += g_blkoff[blockIdx.x];
        g_cursor[i] = 0;
        g_dinv[i] = rsqrtf((float)g_deg[i] + 1.0f);
    }
}
__global__ void k_csrfill() {
    int e = blockIdx.x * blockDim.x + threadIdx.x;
    if (e >= NE) return;
    int s = g_src[e], d = g_dst[e];
    int pos = atomicAdd(&g_cursor[d], 1);
    int slot = g_rowptr[d] + pos;
    g_csrc[slot] = s;
    g_cnrm[slot] = g_dinv[s] * g_dinv[d];
}

// ---------------- all weight transposes + bf16 splits, one kernel ----------------
__global__ void k_wsplit_all(const float* __restrict__ W1, const float* __restrict__ W2,
                             const float* __restrict__ W3) {
    int i = blockIdx.x * blockDim.x + threadIdx.x;
    const int N1 = 128 * 256;
    if (i < N1) {
        int k = i >> 8, n = i & 255;
        float v = W1[i];
        __nv_bfloat16 h = __float2bfloat16(v);
        g_w1hi[(size_t)n * 128 + k] = h;
        g_w1lo[(size_t)n * 128 + k] = __float2bfloat16(v - __bfloat162float(h));
        return;
    }
    i -= N1;
    const int N2 = 256 * 256;
    if (i < N2) {
        int k = i >> 8, n = i & 255;
        float v = W2[i];
        __nv_bfloat16 h = __float2bfloat16(v);
        g_w2hi[(size_t)n * 256 + k] = h;
        g_w2lo[(size_t)n * 256 + k] = __float2bfloat16(v - __bfloat162float(h));
        return;
    }
    i -= N2;
    if (i < N2) {
        int k = i >> 8, n = i & 255;
        float v = W3[i];
        __nv_bfloat16 h = __float2bfloat16(v);
        g_w3hi[(size_t)n * 256 + k] = h;
        g_w3lo[(size_t)n * 256 + k] = __float2bfloat16(v - __bfloat162float(h));
    }
}

// ---------------- mma.sync split-bf16 GEMM: H = act(A) @ W only ----------------
#define TSTR 72
#define SB0  135168
#define SBUF 36864
#define SBLO 18432
#define GEMM_SMEM 208896

__global__ void __launch_bounds__(256, 1)
k_gemm(const float* __restrict__ A,
       const __nv_bfloat16* __restrict__ wt_hi, const __nv_bfloat16* __restrict__ wt_lo,
       float* __restrict__ outH, int M, int K, int relu)
{
    extern __shared__ char smem[];
    uint32_t sb = smem_u32(smem);
    int tid = threadIdx.x;
    int wid = tid >> 5;
    int lane = tid & 31;
    int bm = blockIdx.x * 128;
    int wm = (wid >> 2) * 64;
    int wn = (wid & 3) * 32;

    const int AST = K + 8;
    const uint32_t aLoOff = (uint32_t)(128 * AST * 2);
    const int nch = K >> 6;
    const int ntot = 2 * nch;

    {
        uint32_t base = sb + SB0;
#pragma unroll
        for (int it = 0; it < 4; it++) {
            int idx = tid + it * 256;
            int row = idx >> 3, g = idx & 7;
            uint32_t off = (uint32_t)(row * TSTR + g * 8) * 2;
            cp16(base + off,        wt_hi + (size_t)row * K + g * 8);
            cp16(base + SBLO + off, wt_lo + (size_t)row * K + g * 8);
        }
        CP_COMMIT();
    }

    for (int idx = tid; idx < 128 * (K >> 2); idx += 256) {
        int row = idx / (K >> 2);
        int g   = idx % (K >> 2);
        float4 v = make_float4(0.f, 0.f, 0.f, 0.f);
        int gr = bm + row;
        if (gr < M) v = *(const float4*)(A + (size_t)gr * K + g * 4);
        if (relu) {
            v.x = fmaxf(v.x, 0.f); v.y = fmaxf(v.y, 0.f);
            v.z = fmaxf(v.z, 0.f); v.w = fmaxf(v.w, 0.f);
        }
        __nv_bfloat16 h0 = __float2bfloat16(v.x), h1 = __float2bfloat16(v.y);
        __nv_bfloat16 h2 = __float2bfloat16(v.z), h3 = __float2bfloat16(v.w);
        __nv_bfloat16 l0 = __float2bfloat16(v.x - __bfloat162float(h0));
        __nv_bfloat16 l1 = __float2bfloat16(v.y - __bfloat162float(h1));
        __nv_bfloat16 l2 = __float2bfloat16(v.z - __bfloat162float(h2));
        __nv_bfloat16 l3 = __float2bfloat16(v.w - __bfloat162float(h3));
        uint2 hp, lp;
        hp.x = ((uint32_t)__bfloat16_as_ushort(h1) << 16) | __bfloat16_as_ushort(h0);
        hp.y = ((uint32_t)__bfloat16_as_ushort(h3) << 16) | __bfloat16_as_ushort(h2);
        lp.x = ((uint32_t)__bfloat16_as_ushort(l1) << 16) | __bfloat16_as_ushort(l0);
        lp.y = ((uint32_t)__bfloat16_as_ushort(l3) << 16) | __bfloat16_as_ushort(l2);
        uint32_t off = (uint32_t)(row * AST + g * 4) * 2;
        *(uint2*)(smem + off)          = hp;
        *(uint2*)(smem + aLoOff + off) = lp;
    }

    float acc[4][4][4];
#pragma unroll
    for (int mi = 0; mi < 4; mi++)
#pragma unroll
        for (int ni = 0; ni < 4; ni++)
#pragma unroll
            for (int q = 0; q < 4; q++) acc[mi][ni][q] = 0.0f;

    for (int t = 0; t < ntot; t++) {
        int nh = t / nch, ch = t % nch;

        if (t + 1 < ntot) {
            int nh2 = (t + 1) / nch, ch2 = (t + 1) % nch;
            int n0b = nh2 * 128, k0b = ch2 * 64;
            uint32_t base = sb + SB0 + ((t + 1) & 1) * SBUF;
#pragma unroll
            for (int it = 0; it < 4; it++) {
                int idx = tid + it * 256;
                int row = idx >> 3, g = idx & 7;
                uint32_t off = (uint32_t)(row * TSTR + g * 8) * 2;
                const size_t gsrc = (size_t)(n0b + row) * K + k0b + g * 8;
                cp16(base + off,        wt_hi + gsrc);
                cp16(base + SBLO + off, wt_lo + gsrc);
            }
            CP_COMMIT();
            CP_WAIT(1);
        } else {
            CP_WAIT(0);
        }
        __syncthreads();

        uint32_t bBase = sb + SB0 + (t & 1) * SBUF;
        int k0 = ch * 64;
#pragma unroll
        for (int ks = 0; ks < 4; ks++) {
            int kk = k0 + ks * 16;
            uint32_t ah[4][4], al[4][4], bh[2][4], bl[2][4];
            int arow = (lane & 15);
            int acol = kk + ((lane >> 4) << 3);
#pragma unroll
            for (int mi = 0; mi < 4; mi++) {
                uint32_t off = (uint32_t)((wm + mi * 16 + arow) * AST + acol) * 2;
                ldmat_x4(ah[mi], sb + off);
                ldmat_x4(al[mi], sb + aLoOff + off);
            }
            int brow = ((lane >> 4) << 3) + (lane & 7);
            int bcol = ks * 16 + ((lane >> 3) & 1) * 8;
#pragma unroll
            for (int j = 0; j < 2; j++) {
                uint32_t off = (uint32_t)((wn + 16 * j + brow) * TSTR + bcol) * 2;
                ldmat_x4(bh[j], bBase + off);
                ldmat_x4(bl[j], bBase + SBLO + off);
            }
#pragma unroll
            for (int mi = 0; mi < 4; mi++) {
#pragma unroll
                for (int ni = 0; ni < 4; ni++) {
                    const uint32_t* bhp = &bh[ni >> 1][(ni & 1) * 2];
                    const uint32_t* blp = &bl[ni >> 1][(ni & 1) * 2];
                    mma16816(acc[mi][ni], ah[mi], bhp);
                    mma16816(acc[mi][ni], ah[mi], blp);
                    mma16816(acc[mi][ni], al[mi], bhp);
                }
            }
        }

        if (ch == nch - 1) {
            int n0 = nh * 128;
            int g = lane >> 2, tg = lane & 3;
#pragma unroll
            for (int mi = 0; mi < 4; mi++) {
                int r0 = bm + wm + mi * 16 + g;
                int r1 = r0 + 8;
#pragma unroll
                for (int ni = 0; ni < 4; ni++) {
                    int col = n0 + wn + ni * 8 + tg * 2;
                    float* c = acc[mi][ni];
                    if (r0 < M)
                        *(float2*)(outH + (size_t)r0 * 256 + col) = make_float2(c[0], c[1]);
                    if (r1 < M)
                        *(float2*)(outH + (size_t)r1 * 256 + col) = make_float2(c[2], c[3]);
                    c[0] = c[1] = c[2] = c[3] = 0.f;
                }
            }
        }
        __syncthreads();
    }
}

// ---------------- CSR gather: init from own H row + bias, add neighbors ---------
__global__ void __launch_bounds__(256) k_gather(const float* __restrict__ bias,
                                                float* __restrict__ outA) {
    int node = blockIdx.x * 8 + (threadIdx.x >> 5);
    int lane = threadIdx.x & 31;
    if (node >= NN) return;
    int beg = g_rowptr[node];
    int dg  = g_deg[node];
    float di = g_dinv[node];
    float nrm2 = di * di;
    const float4* hrow = (const float4*)(g_bufH + (size_t)node * FDIM);
    const float4* bias4 = (const float4*)bias;
    float4 h0 = hrow[lane];
    float4 h1 = hrow[lane + 32];
    float4 b0 = __ldg(&bias4[lane]);
    float4 b1 = __ldg(&bias4[lane + 32]);
    float4 a0, a1;
    a0.x = h0.x * nrm2 + b0.x; a0.y = h0.y * nrm2 + b0.y;
    a0.z = h0.z * nrm2 + b0.z; a0.w = h0.w * nrm2 + b0.w;
    a1.x = h1.x * nrm2 + b1.x; a1.y = h1.y * nrm2 + b1.y;
    a1.z = h1.z * nrm2 + b1.z; a1.w = h1.w * nrm2 + b1.w;
    int j = 0;
    for (; j + 1 < dg; j += 2) {
        int s0 = __ldg(&g_csrc[beg + j]);
        int s1 = __ldg(&g_csrc[beg + j + 1]);
        float n0 = __ldg(&g_cnrm[beg + j]);
        float n1 = __ldg(&g_cnrm[beg + j + 1]);
        const float4* p0 = (const float4*)(g_bufH + (size_t)s0 * FDIM);
        const float4* p1 = (const float4*)(g_bufH + (size_t)s1 * FDIM);
        float4 u0 = p0[lane], u1 = p0[lane + 32];
        float4 w0 = p1[lane], w1 = p1[lane + 32];
        a0.x += u0.x * n0; a0.y += u0.y * n0; a0.z += u0.z * n0; a0.w += u0.w * n0;
        a1.x += u1.x * n0; a1.y += u1.y * n0; a1.z += u1.z * n0; a1.w += u1.w * n0;
        a0.x += w0.x * n1; a0.y += w0.y * n1; a0.z += w0.z * n1; a0.w += w0.w * n1;
        a1.x += w1.x * n1; a1.y += w1.y * n1; a1.z += w1.z * n1; a1.w += w1.w * n1;
    }
    if (j < dg) {
        int s = __ldg(&g_csrc[beg + j]);
        float nm = __ldg(&g_cnrm[beg + j]);
        const float4* p = (const float4*)(g_bufH + (size_t)s * FDIM);
        float4 v0 = p[lane], v1 = p[lane + 32];
        a0.x += v0.x * nm; a0.y += v0.y * nm; a0.z += v0.z * nm; a0.w += v0.w * nm;
        a1.x += v1.x * nm; a1.y += v1.y * nm; a1.z += v1.z * nm; a1.w += v1.w * nm;
    }
    float4* row = (float4*)(outA + (size_t)node * FDIM);
    row[lane]      = a0;
    row[lane + 32] = a1;
}

// ---------------- segment pooling (batch sorted) + FC ----------------
__device__ __forceinline__ int lbound(const int* a, int n, int key) {
    int lo = 0, hi = n;
    while (lo < hi) { int m = (lo + hi) >> 1; if (a[m] < key) lo = m + 1; else hi = m; }
    return lo;
}

__global__ void k_pool(const float* __restrict__ in) {
    __shared__ int bnd[2];
    int g = blockIdx.x;
    int t = threadIdx.x;
    if (t == 0) bnd[0] = lbound(g_batch, NN, g);
    if (t == 1) bnd[1] = lbound(g_batch, NN, g + 1);
    __syncthreads();
    int lo = bnd[0], hi = bnd[1];
    float acc = 0.f;
    for (int n = lo; n < hi; n++)
        acc += fmaxf(in[(size_t)n * FDIM + t], 0.f);
    int cnt = hi - lo;
    g_pool[(size_t)g * FDIM + t] = cnt > 0 ? acc / (float)cnt : 0.f;
}

__global__ void k_fc(const float* __restrict__ Wfc, const float* __restrict__ bfc,
                     float* __restrict__ out) {
    __shared__ float sp[FDIM];
    int g = blockIdx.x;
    for (int f = threadIdx.x; f < FDIM; f += 128)
        sp[f] = g_pool[(size_t)g * FDIM + f];
    __syncthreads();
    int j = threadIdx.x;
    float acc = bfc[j];
#pragma unroll 4
    for (int f = 0; f < FDIM; f++) acc += sp[f] * Wfc[(size_t)f * FOUT + j];
    out[(size_t)g * FOUT + j] = acc;
}

// ---------------- launch ----------------
extern "C" void kernel_launch(void* const* d_in, const int* in_sizes, int n_in,
                              void* d_out, int out_size) {
    (void)in_sizes; (void)n_in; (void)out_size;
    const float* x   = (const float*)d_in[0];
    const void*  ei  = d_in[1];
    const void*  bt  = d_in[2];
    const float* W1  = (const float*)d_in[3];
    const float* b1  = (const float*)d_in[4];
    const float* W2  = (const float*)d_in[5];
    const float* b2  = (const float*)d_in[6];
    const float* W3  = (const float*)d_in[7];
    const float* b3  = (const float*)d_in[8];
    const float* Wfc = (const float*)d_in[9];
    const float* bfc = (const float*)d_in[10];
    float* out = (float*)d_out;

    float *buf0 = nullptr, *buf1 = nullptr, *bufH = nullptr;
    cudaGetSymbolAddress((void**)&buf0, g_buf0);
    cudaGetSymbolAddress((void**)&buf1, g_buf1);
    cudaGetSymbolAddress((void**)&bufH, g_bufH);
    __nv_bfloat16 *w1h, *w1l, *w2h, *w2l, *w3h, *w3l;
    cudaGetSymbolAddress((void**)&w1h, g_w1hi);
    cudaGetSymbolAddress((void**)&w1l, g_w1lo);
    cudaGetSymbolAddress((void**)&w2h, g_w2hi);
    cudaGetSymbolAddress((void**)&w2l, g_w2lo);
    cudaGetSymbolAddress((void**)&w3h, g_w3hi);
    cudaGetSymbolAddress((void**)&w3l, g_w3lo);

    cudaFuncSetAttribute(k_gemm, cudaFuncAttributeMaxDynamicSharedMemorySize, GEMM_SMEM);

    // prep + CSR build + weight splits
    k_zero<<<NBLK, 256>>>();
    k_prep<<<(NE + 255) / 256, 256>>>(ei, bt);
    k_scan1<<<NBLK, 256>>>();
    k_scan2<<<1, 512>>>();
    k_scan3<<<NBLK, 256>>>();
    k_csrfill<<<(NE + 255) / 256, 256>>>();
    k_wsplit_all<<<(128 * 256 + 2 * 256 * 256 + 255) / 256, 256>>>(W1, W2, W3);

    const int gemm_grid = (NN + 127) / 128;
    const int gat_grid  = (NN + 7) / 8;

    // layer 1 (K=128): x -> H -> buf0
    k_gemm<<<gemm_grid, 256, GEMM_SMEM>>>(x, w1h, w1l, bufH, NN, 128, 0);
    k_gather<<<gat_grid, 256>>>(b1, buf0);
    // layer 2 (K=256): buf0 -> H -> buf1
    k_gemm<<<gemm_grid, 256, GEMM_SMEM>>>(buf0, w2h, w2l, bufH, NN, 256, 1);
    k_gather<<<gat_grid, 256>>>(b2, buf1);
    // layer 3 (K=256): buf1 -> H -> buf0
    k_gemm<<<gemm_grid, 256, GEMM_SMEM>>>(buf1, w3h, w3l, bufH, NN, 256, 1);
    k_gather<<<gat_grid, 256>>>(b3, buf0);

    // pool + fc
    k_pool<<<NG, FDIM>>>(buf0);
    k_fc<<<NG, 128>>>(Wfc, bfc, out);
}

// round 8
// speedup vs baseline: 2.5650x; 1.1662x over previous
#include <cuda_runtime.h>
#include <cuda_bf16.h>
#include <math.h>
#include <stdint.h>

#define NN 100000
#define NE 320000
#define NG 512
#define FDIM 256
#define FOUT 128
#define NBLK 391   // ceil(NN/256)

// ---------------- scratch (static device memory; no allocation) ----------------
__device__ __align__(16) float g_bufH[(size_t)NN * FDIM];          // GEMM output (f32)
__device__ __align__(16) __nv_bfloat16 g_ahi[(size_t)(NN + 128) * FDIM]; // layer input hi
__device__ __align__(16) __nv_bfloat16 g_alo[(size_t)(NN + 128) * FDIM]; // layer input lo
__device__ float g_dinv[NN];
__device__ int   g_deg[NN];
__device__ int   g_rowptr[NN];
__device__ int   g_cursor[NN];
__device__ int   g_blksum[512];
__device__ int   g_blkoff[512];
__device__ int   g_csrc[NE];
__device__ float g_cnrm[NE];
__device__ int   g_src[NE];
__device__ int   g_dst[NE];
__device__ int   g_batch[NN];
__device__ float g_pool[NG * FDIM];
__device__ __align__(16) __nv_bfloat16 g_w1hi[128 * 256];
__device__ __align__(16) __nv_bfloat16 g_w1lo[128 * 256];
__device__ __align__(16) __nv_bfloat16 g_w2hi[256 * 256];
__device__ __align__(16) __nv_bfloat16 g_w2lo[256 * 256];
__device__ __align__(16) __nv_bfloat16 g_w3hi[256 * 256];
__device__ __align__(16) __nv_bfloat16 g_w3lo[256 * 256];

// ---------------- helpers ----------------
__device__ __forceinline__ uint32_t smem_u32(const void* p) {
    uint32_t a;
    asm("{ .reg .u64 t; cvta.to.shared.u64 t, %1; cvt.u32.u64 %0, t; }" : "=r"(a) : "l"(p));
    return a;
}
__device__ __forceinline__ void ldmat_x4(uint32_t* r, uint32_t addr) {
    asm volatile("ldmatrix.sync.aligned.m8n8.x4.shared.b16 {%0,%1,%2,%3}, [%4];"
                 : "=r"(r[0]), "=r"(r[1]), "=r"(r[2]), "=r"(r[3]) : "r"(addr));
}
__device__ __forceinline__ void mma16816(float* c, const uint32_t* a, const uint32_t* b) {
    asm volatile("mma.sync.aligned.m16n8k16.row.col.f32.bf16.bf16.f32 "
                 "{%0,%1,%2,%3}, {%4,%5,%6,%7}, {%8,%9}, {%0,%1,%2,%3};"
                 : "+f"(c[0]), "+f"(c[1]), "+f"(c[2]), "+f"(c[3])
                 : "r"(a[0]), "r"(a[1]), "r"(a[2]), "r"(a[3]), "r"(b[0]), "r"(b[1]));
}
__device__ __forceinline__ void cp16(uint32_t smem_addr, const void* gptr) {
    asm volatile("cp.async.cg.shared.global [%0], [%1], 16;" :: "r"(smem_addr), "l"(gptr));
}
#define CP_COMMIT() asm volatile("cp.async.commit_group;" ::: "memory")
#define CP_WAIT(n)  asm volatile("cp.async.wait_group %0;" :: "n"(n) : "memory")

// split a float4 into packed bf16 hi (uint2) and lo (uint2)
__device__ __forceinline__ void split4(float4 v, uint2& hp, uint2& lp) {
    __nv_bfloat16 h0 = __float2bfloat16(v.x), h1 = __float2bfloat16(v.y);
    __nv_bfloat16 h2 = __float2bfloat16(v.z), h3 = __float2bfloat16(v.w);
    __nv_bfloat16 l0 = __float2bfloat16(v.x - __bfloat162float(h0));
    __nv_bfloat16 l1 = __float2bfloat16(v.y - __bfloat162float(h1));
    __nv_bfloat16 l2 = __float2bfloat16(v.z - __bfloat162float(h2));
    __nv_bfloat16 l3 = __float2bfloat16(v.w - __bfloat162float(h3));
    hp.x = ((uint32_t)__bfloat16_as_ushort(h1) << 16) | __bfloat16_as_ushort(h0);
    hp.y = ((uint32_t)__bfloat16_as_ushort(h3) << 16) | __bfloat16_as_ushort(h2);
    lp.x = ((uint32_t)__bfloat16_as_ushort(l1) << 16) | __bfloat16_as_ushort(l0);
    lp.y = ((uint32_t)__bfloat16_as_ushort(l3) << 16) | __bfloat16_as_ushort(l2);
}

// ---------------- prep: zero, convert+detect+degree ----------------
__global__ void k_zero() {
    int i = blockIdx.x * blockDim.x + threadIdx.x;
    if (i < NN) g_deg[i] = 0;
}

__global__ void k_prep(const void* e, const void* b) {
    __shared__ int s64;
    if (threadIdx.x == 0) {
        const long long* p = (const long long*)e;
        int is64 = 1;
        for (int t = 0; t < 16; t++) {
            long long v = p[t];
            if (v < 0 || v >= NN) is64 = 0;
        }
        s64 = is64;
    }
    __syncthreads();
    int f64 = s64;
    int i = blockIdx.x * blockDim.x + threadIdx.x;
    if (i < NE) {
        int s, d;
        if (f64) {
            const long long* p = (const long long*)e;
            s = (int)p[i]; d = (int)p[NE + i];
        } else {
            const int* p = (const int*)e;
            s = p[i]; d = p[NE + i];
        }
        g_src[i] = s;
        g_dst[i] = d;
        atomicAdd(&g_deg[d], 1);
    }
    if (i < NN) {
        if (f64) g_batch[i] = (int)((const long long*)b)[i];
        else     g_batch[i] = ((const int*)b)[i];
    }
}

// ---------------- CSR build ----------------
__global__ void k_scan1() {
    __shared__ int s[256];
    int tid = threadIdx.x;
    int i = blockIdx.x * 256 + tid;
    int v = (i < NN) ? g_deg[i] : 0;
    s[tid] = v;
#pragma unroll
    for (int off = 1; off < 256; off <<= 1) {
        __syncthreads();
        int t = (tid >= off) ? s[tid - off] : 0;
        __syncthreads();
        s[tid] += t;
    }
    __syncthreads();
    if (i < NN) g_rowptr[i] = s[tid] - v;
    if (tid == 255) g_blksum[blockIdx.x] = s[255];
}
__global__ void k_scan2() {
    __shared__ int s[512];
    int tid = threadIdx.x;
    int v = (tid < NBLK) ? g_blksum[tid] : 0;
    s[tid] = v;
#pragma unroll
    for (int off = 1; off < 512; off <<= 1) {
        __syncthreads();
        int t = (tid >= off) ? s[tid - off] : 0;
        __syncthreads();
        s[tid] += t;
    }
    __syncthreads();
    g_blkoff[tid] = s[tid] - v;
}
__global__ void k_scan3() {
    int i = blockIdx.x * 256 + threadIdx.x;
    if (i < NN) {
        g_rowptr[i] += g_blkoff[blockIdx.x];
        g_cursor[i] = 0;
        g_dinv[i] = rsqrtf((float)g_deg[i] + 1.0f);
    }
}
__global__ void k_csrfill() {
    int e = blockIdx.x * blockDim.x + threadIdx.x;
    if (e >= NE) return;
    int s = g_src[e], d = g_dst[e];
    int pos = atomicAdd(&g_cursor[d], 1);
    int slot = g_rowptr[d] + pos;
    g_csrc[slot] = s;
    g_cnrm[slot] = g_dinv[s] * g_dinv[d];
}

// ---------------- weight transposes + bf16 splits ----------------
__global__ void k_wsplit_all(const float* __restrict__ W1, const float* __restrict__ W2,
                             const float* __restrict__ W3) {
    int i = blockIdx.x * blockDim.x + threadIdx.x;
    const int N1 = 128 * 256;
    if (i < N1) {
        int k = i >> 8, n = i & 255;
        float v = W1[i];
        __nv_bfloat16 h = __float2bfloat16(v);
        g_w1hi[(size_t)n * 128 + k] = h;
        g_w1lo[(size_t)n * 128 + k] = __float2bfloat16(v - __bfloat162float(h));
        return;
    }
    i -= N1;
    const int N2 = 256 * 256;
    if (i < N2) {
        int k = i >> 8, n = i & 255;
        float v = W2[i];
        __nv_bfloat16 h = __float2bfloat16(v);
        g_w2hi[(size_t)n * 256 + k] = h;
        g_w2lo[(size_t)n * 256 + k] = __float2bfloat16(v - __bfloat162float(h));
        return;
    }
    i -= N2;
    if (i < N2) {
        int k = i >> 8, n = i & 255;
        float v = W3[i];
        __nv_bfloat16 h = __float2bfloat16(v);
        g_w3hi[(size_t)n * 256 + k] = h;
        g_w3lo[(size_t)n * 256 + k] = __float2bfloat16(v - __bfloat162float(h));
    }
}

// ---------------- x -> bf16 hi/lo (layer-1 input; no relu) ----------------
__global__ void k_xsplit(const float* __restrict__ x) {
    int i = blockIdx.x * blockDim.x + threadIdx.x;   // over NN*32 float4s
    if (i >= NN * 32) return;
    float4 v = *(const float4*)(x + (size_t)i * 4);
    uint2 hp, lp;
    split4(v, hp, lp);
    ((uint2*)g_ahi)[i] = hp;
    ((uint2*)g_alo)[i] = lp;
}

// ---------------- pure-bf16 mma.sync GEMM, cp.async double-buffered A+B --------
// H[M,256] = A @ W, A given as bf16 hi/lo [M,K] global (pre-activated).
#define TSTR 72
#define ABUF 36864          // one A stage (hi+lo)
#define SPLO 18432          // lo offset within a stage
#define SB0  73728          // B stages start
#define GEMM_SMEM 147456

__global__ void __launch_bounds__(256, 1)
k_gemm(const __nv_bfloat16* __restrict__ ahi, const __nv_bfloat16* __restrict__ alo,
       const __nv_bfloat16* __restrict__ wt_hi, const __nv_bfloat16* __restrict__ wt_lo,
       float* __restrict__ outH, int M, int K)
{
    extern __shared__ char smem[];
    uint32_t sb = smem_u32(smem);
    int tid = threadIdx.x;
    int wid = tid >> 5;
    int lane = tid & 31;
    int bm = blockIdx.x * 128;
    int wm = (wid >> 2) * 64;
    int wn = (wid & 3) * 32;

    const int nch = K >> 6;
    const int ntot = 2 * nch;

    // stage(tt): A chunk + B chunk into buffer tt&1
#define STAGE(tt) do {                                                          \
        int nh2 = (tt) / nch, ch2 = (tt) % nch;                                 \
        int k0b = ch2 * 64, n0b = nh2 * 128;                                    \
        uint32_t abase = sb + ((tt) & 1) * ABUF;                                \
        uint32_t bbase = sb + SB0 + ((tt) & 1) * ABUF;                          \
        _Pragma("unroll")                                                       \
        for (int it = 0; it < 4; it++) {                                        \
            int idx = tid + it * 256;                                           \
            int row = idx >> 3, g = idx & 7;                                    \
            uint32_t off = (uint32_t)(row * TSTR + g * 8) * 2;                  \
            size_t asrc = (size_t)(bm + row) * K + k0b + g * 8;                 \
            size_t bsrc = (size_t)(n0b + row) * K + k0b + g * 8;                \
            cp16(abase + off,        ahi + asrc);                               \
            cp16(abase + SPLO + off, alo + asrc);                               \
            cp16(bbase + off,        wt_hi + bsrc);                             \
            cp16(bbase + SPLO + off, wt_lo + bsrc);                             \
        }                                                                       \
        CP_COMMIT();                                                            \
    } while (0)

    STAGE(0);

    float acc[4][4][4];
#pragma unroll
    for (int mi = 0; mi < 4; mi++)
#pragma unroll
        for (int ni = 0; ni < 4; ni++)
#pragma unroll
            for (int q = 0; q < 4; q++) acc[mi][ni][q] = 0.0f;

    for (int t = 0; t < ntot; t++) {
        int nh = t / nch, ch = t % nch;

        if (t + 1 < ntot) { STAGE(t + 1); CP_WAIT(1); }
        else              { CP_WAIT(0); }
        __syncthreads();

        uint32_t aBase = sb + (t & 1) * ABUF;
        uint32_t bBase = sb + SB0 + (t & 1) * ABUF;
#pragma unroll
        for (int ks = 0; ks < 4; ks++) {
            uint32_t ah[4][4], al[4][4], bh[2][4], bl[2][4];
            int arow = (lane & 15);
            int acol = ks * 16 + ((lane >> 4) << 3);
#pragma unroll
            for (int mi = 0; mi < 4; mi++) {
                uint32_t off = (uint32_t)((wm + mi * 16 + arow) * TSTR + acol) * 2;
                ldmat_x4(ah[mi], aBase + off);
                ldmat_x4(al[mi], aBase + SPLO + off);
            }
            int brow = ((lane >> 4) << 3) + (lane & 7);
            int bcol = ks * 16 + ((lane >> 3) & 1) * 8;
#pragma unroll
            for (int j = 0; j < 2; j++) {
                uint32_t off = (uint32_t)((wn + 16 * j + brow) * TSTR + bcol) * 2;
                ldmat_x4(bh[j], bBase + off);
                ldmat_x4(bl[j], bBase + SPLO + off);
            }
#pragma unroll
            for (int mi = 0; mi < 4; mi++) {
#pragma unroll
                for (int ni = 0; ni < 4; ni++) {
                    const uint32_t* bhp = &bh[ni >> 1][(ni & 1) * 2];
                    const uint32_t* blp = &bl[ni >> 1][(ni & 1) * 2];
                    mma16816(acc[mi][ni], ah[mi], bhp);
                    mma16816(acc[mi][ni], ah[mi], blp);
                    mma16816(acc[mi][ni], al[mi], bhp);
                }
            }
        }

        if (ch == nch - 1) {
            int n0 = nh * 128;
            int g = lane >> 2, tg = lane & 3;
#pragma unroll
            for (int mi = 0; mi < 4; mi++) {
                int r0 = bm + wm + mi * 16 + g;
                int r1 = r0 + 8;
#pragma unroll
                for (int ni = 0; ni < 4; ni++) {
                    int col = n0 + wn + ni * 8 + tg * 2;
                    float* c = acc[mi][ni];
                    if (r0 < M)
                        *(float2*)(outH + (size_t)r0 * 256 + col) = make_float2(c[0], c[1]);
                    if (r1 < M)
                        *(float2*)(outH + (size_t)r1 * 256 + col) = make_float2(c[2], c[3]);
                    c[0] = c[1] = c[2] = c[3] = 0.f;
                }
            }
        }
        __syncthreads();
    }
#undef STAGE
}

// ---------------- CSR gather: H + bias + neighbors -> relu -> bf16 hi/lo -------
__global__ void __launch_bounds__(256) k_gather(const float* __restrict__ bias) {
    int node = blockIdx.x * 8 + (threadIdx.x >> 5);
    int lane = threadIdx.x & 31;
    if (node >= NN) return;
    int beg = g_rowptr[node];
    int dg  = g_deg[node];
    float di = g_dinv[node];
    float nrm2 = di * di;
    const float4* hrow = (const float4*)(g_bufH + (size_t)node * FDIM);
    const float4* bias4 = (const float4*)bias;
    float4 h0 = hrow[lane];
    float4 h1 = hrow[lane + 32];
    float4 b0 = __ldg(&bias4[lane]);
    float4 b1 = __ldg(&bias4[lane + 32]);
    float4 a0, a1;
    a0.x = h0.x * nrm2 + b0.x; a0.y = h0.y * nrm2 + b0.y;
    a0.z = h0.z * nrm2 + b0.z; a0.w = h0.w * nrm2 + b0.w;
    a1.x = h1.x * nrm2 + b1.x; a1.y = h1.y * nrm2 + b1.y;
    a1.z = h1.z * nrm2 + b1.z; a1.w = h1.w * nrm2 + b1.w;
    int j = 0;
    for (; j + 1 < dg; j += 2) {
        int s0 = __ldg(&g_csrc[beg + j]);
        int s1 = __ldg(&g_csrc[beg + j + 1]);
        float n0 = __ldg(&g_cnrm[beg + j]);
        float n1 = __ldg(&g_cnrm[beg + j + 1]);
        const float4* p0 = (const float4*)(g_bufH + (size_t)s0 * FDIM);
        const float4* p1 = (const float4*)(g_bufH + (size_t)s1 * FDIM);
        float4 u0 = p0[lane], u1 = p0[lane + 32];
        float4 w0 = p1[lane], w1 = p1[lane + 32];
        a0.x += u0.x * n0; a0.y += u0.y * n0; a0.z += u0.z * n0; a0.w += u0.w * n0;
        a1.x += u1.x * n0; a1.y += u1.y * n0; a1.z += u1.z * n0; a1.w += u1.w * n0;
        a0.x += w0.x * n1; a0.y += w0.y * n1; a0.z += w0.z * n1; a0.w += w0.w * n1;
        a1.x += w1.x * n1; a1.y += w1.y * n1; a1.z += w1.z * n1; a1.w += w1.w * n1;
    }
    if (j < dg) {
        int s = __ldg(&g_csrc[beg + j]);
        float nm = __ldg(&g_cnrm[beg + j]);
        const float4* p = (const float4*)(g_bufH + (size_t)s * FDIM);
        float4 v0 = p[lane], v1 = p[lane + 32];
        a0.x += v0.x * nm; a0.y += v0.y * nm; a0.z += v0.z * nm; a0.w += v0.w * nm;
        a1.x += v1.x * nm; a1.y += v1.y * nm; a1.z += v1.z * nm; a1.w += v1.w * nm;
    }
    // ReLU + split to bf16 hi/lo
    a0.x = fmaxf(a0.x, 0.f); a0.y = fmaxf(a0.y, 0.f);
    a0.z = fmaxf(a0.z, 0.f); a0.w = fmaxf(a0.w, 0.f);
    a1.x = fmaxf(a1.x, 0.f); a1.y = fmaxf(a1.y, 0.f);
    a1.z = fmaxf(a1.z, 0.f); a1.w = fmaxf(a1.w, 0.f);
    uint2 hp0, lp0, hp1, lp1;
    split4(a0, hp0, lp0);
    split4(a1, hp1, lp1);
    uint2* hi = (uint2*)(g_ahi + (size_t)node * FDIM);
    uint2* lo = (uint2*)(g_alo + (size_t)node * FDIM);
    hi[lane]      = hp0;
    hi[lane + 32] = hp1;
    lo[lane]      = lp0;
    lo[lane + 32] = lp1;
}

// ---------------- segment pooling (batch sorted) + FC ----------------
__device__ __forceinline__ int lbound(const int* a, int n, int key) {
    int lo = 0, hi = n;
    while (lo < hi) { int m = (lo + hi) >> 1; if (a[m] < key) lo = m + 1; else hi = m; }
    return lo;
}

__global__ void k_pool() {
    __shared__ int bnd[2];
    int g = blockIdx.x;
    int t = threadIdx.x;
    if (t == 0) bnd[0] = lbound(g_batch, NN, g);
    if (t == 1) bnd[1] = lbound(g_batch, NN, g + 1);
    __syncthreads();
    int lo = bnd[0], hi = bnd[1];
    float acc = 0.f;
    for (int n = lo; n < hi; n++) {
        float v = __bfloat162float(g_ahi[(size_t)n * FDIM + t]) +
                  __bfloat162float(g_alo[(size_t)n * FDIM + t]);
        acc += fmaxf(v, 0.f);
    }
    int cnt = hi - lo;
    g_pool[(size_t)g * FDIM + t] = cnt > 0 ? acc / (float)cnt : 0.f;
}

__global__ void k_fc(const float* __restrict__ Wfc, const float* __restrict__ bfc,
                     float* __restrict__ out) {
    __shared__ float sp[FDIM];
    int g = blockIdx.x;
    for (int f = threadIdx.x; f < FDIM; f += 128)
        sp[f] = g_pool[(size_t)g * FDIM + f];
    __syncthreads();
    int j = threadIdx.x;
    float acc = bfc[j];
#pragma unroll 4
    for (int f = 0; f < FDIM; f++) acc += sp[f] * Wfc[(size_t)f * FOUT + j];
    out[(size_t)g * FOUT + j] = acc;
}

// ---------------- launch ----------------
extern "C" void kernel_launch(void* const* d_in, const int* in_sizes, int n_in,
                              void* d_out, int out_size) {
    (void)in_sizes; (void)n_in; (void)out_size;
    const float* x   = (const float*)d_in[0];
    const void*  ei  = d_in[1];
    const void*  bt  = d_in[2];
    const float* W1  = (const float*)d_in[3];
    const float* b1  = (const float*)d_in[4];
    const float* W2  = (const float*)d_in[5];
    const float* b2  = (const float*)d_in[6];
    const float* W3  = (const float*)d_in[7];
    const float* b3  = (const float*)d_in[8];
    const float* Wfc = (const float*)d_in[9];
    const float* bfc = (const float*)d_in[10];
    float* out = (float*)d_out;

    float* bufH = nullptr;
    cudaGetSymbolAddress((void**)&bufH, g_bufH);
    __nv_bfloat16 *ahi, *alo, *w1h, *w1l, *w2h, *w2l, *w3h, *w3l;
    cudaGetSymbolAddress((void**)&ahi, g_ahi);
    cudaGetSymbolAddress((void**)&alo, g_alo);
    cudaGetSymbolAddress((void**)&w1h, g_w1hi);
    cudaGetSymbolAddress((void**)&w1l, g_w1lo);
    cudaGetSymbolAddress((void**)&w2h, g_w2hi);
    cudaGetSymbolAddress((void**)&w2l, g_w2lo);
    cudaGetSymbolAddress((void**)&w3h, g_w3hi);
    cudaGetSymbolAddress((void**)&w3l, g_w3lo);

    cudaFuncSetAttribute(k_gemm, cudaFuncAttributeMaxDynamicSharedMemorySize, GEMM_SMEM);

    // prep + CSR build + weight/input splits
    k_zero<<<NBLK, 256>>>();
    k_prep<<<(NE + 255) / 256, 256>>>(ei, bt);
    k_scan1<<<NBLK, 256>>>();
    k_scan2<<<1, 512>>>();
    k_scan3<<<NBLK, 256>>>();
    k_csrfill<<<(NE + 255) / 256, 256>>>();
    k_wsplit_all<<<(128 * 256 + 2 * 256 * 256 + 255) / 256, 256>>>(W1, W2, W3);
    k_xsplit<<<(NN * 32 + 255) / 256, 256>>>(x);

    const int gemm_grid = (NN + 127) / 128;
    const int gat_grid  = (NN + 7) / 8;

    // layer 1 (K=128)
    k_gemm<<<gemm_grid, 256, GEMM_SMEM>>>(ahi, alo, w1h, w1l, bufH, NN, 128);
    k_gather<<<gat_grid, 256>>>(b1);
    // layer 2 (K=256)
    k_gemm<<<gemm_grid, 256, GEMM_SMEM>>>(ahi, alo, w2h, w2l, bufH, NN, 256);
    k_gather<<<gat_grid, 256>>>(b2);
    // layer 3 (K=256)
    k_gemm<<<gemm_grid, 256, GEMM_SMEM>>>(ahi, alo, w3h, w3l, bufH, NN, 256);
    k_gather<<<gat_grid, 256>>>(b3);

    // pool + fc
    k_pool<<<NG, FDIM>>>();
    k_fc<<<NG, 128>>>(Wfc, bfc, out);
}

// round 9
// speedup vs baseline: 2.7418x; 1.0689x over previous
#include <cuda_runtime.h>
#include <cuda_bf16.h>
#include <math.h>
#include <stdint.h>

#define NN 100000
#define NE 320000
#define NG 512
#define FDIM 256
#define FOUT 128
#define NBLK 391   // ceil(NN/256)

// ---------------- scratch (static device memory; no allocation) ----------------
__device__ __align__(16) float g_bufH[(size_t)NN * FDIM];
__device__ __align__(16) __nv_bfloat16 g_ahi[(size_t)(NN + 128) * FDIM];
__device__ __align__(16) __nv_bfloat16 g_alo[(size_t)(NN + 128) * FDIM];
__device__ float g_dinv[NN];
__device__ int   g_deg[NN];
__device__ int   g_rowptr[NN];
__device__ int   g_cursor[NN];
__device__ int   g_blksum[512];
__device__ int   g_blkoff[512];
__device__ int   g_csrc[NE];
__device__ float g_cnrm[NE];
__device__ int   g_src[NE];
__device__ int   g_dst[NE];
__device__ int   g_batch[NN];
__device__ __align__(16) __nv_bfloat16 g_w1hi[128 * 256];
__device__ __align__(16) __nv_bfloat16 g_w1lo[128 * 256];
__device__ __align__(16) __nv_bfloat16 g_w2hi[256 * 256];
__device__ __align__(16) __nv_bfloat16 g_w2lo[256 * 256];
__device__ __align__(16) __nv_bfloat16 g_w3hi[256 * 256];
__device__ __align__(16) __nv_bfloat16 g_w3lo[256 * 256];

// ---------------- helpers ----------------
__device__ __forceinline__ uint32_t smem_u32(const void* p) {
    uint32_t a;
    asm("{ .reg .u64 t; cvta.to.shared.u64 t, %1; cvt.u32.u64 %0, t; }" : "=r"(a) : "l"(p));
    return a;
}
__device__ __forceinline__ void ldmat_x4(uint32_t* r, uint32_t addr) {
    asm volatile("ldmatrix.sync.aligned.m8n8.x4.shared.b16 {%0,%1,%2,%3}, [%4];"
                 : "=r"(r[0]), "=r"(r[1]), "=r"(r[2]), "=r"(r[3]) : "r"(addr));
}
__device__ __forceinline__ void mma16816(float* c, const uint32_t* a, const uint32_t* b) {
    asm volatile("mma.sync.aligned.m16n8k16.row.col.f32.bf16.bf16.f32 "
                 "{%0,%1,%2,%3}, {%4,%5,%6,%7}, {%8,%9}, {%0,%1,%2,%3};"
                 : "+f"(c[0]), "+f"(c[1]), "+f"(c[2]), "+f"(c[3])
                 : "r"(a[0]), "r"(a[1]), "r"(a[2]), "r"(a[3]), "r"(b[0]), "r"(b[1]));
}
__device__ __forceinline__ void cp16(uint32_t smem_addr, const void* gptr) {
    asm volatile("cp.async.cg.shared.global [%0], [%1], 16;" :: "r"(smem_addr), "l"(gptr));
}
#define CP_COMMIT() asm volatile("cp.async.commit_group;" ::: "memory")
#define CP_WAIT(n)  asm volatile("cp.async.wait_group %0;" :: "n"(n) : "memory")

__device__ __forceinline__ void split4(float4 v, uint2& hp, uint2& lp) {
    __nv_bfloat16 h0 = __float2bfloat16(v.x), h1 = __float2bfloat16(v.y);
    __nv_bfloat16 h2 = __float2bfloat16(v.z), h3 = __float2bfloat16(v.w);
    __nv_bfloat16 l0 = __float2bfloat16(v.x - __bfloat162float(h0));
    __nv_bfloat16 l1 = __float2bfloat16(v.y - __bfloat162float(h1));
    __nv_bfloat16 l2 = __float2bfloat16(v.z - __bfloat162float(h2));
    __nv_bfloat16 l3 = __float2bfloat16(v.w - __bfloat162float(h3));
    hp.x = ((uint32_t)__bfloat16_as_ushort(h1) << 16) | __bfloat16_as_ushort(h0);
    hp.y = ((uint32_t)__bfloat16_as_ushort(h3) << 16) | __bfloat16_as_ushort(h2);
    lp.x = ((uint32_t)__bfloat16_as_ushort(l1) << 16) | __bfloat16_as_ushort(l0);
    lp.y = ((uint32_t)__bfloat16_as_ushort(l3) << 16) | __bfloat16_as_ushort(l2);
}

// ---------------- prep ----------------
__global__ void k_zero() {
    int i = blockIdx.x * blockDim.x + threadIdx.x;
    if (i < NN) g_deg[i] = 0;
}

__global__ void k_prep(const void* e, const void* b) {
    __shared__ int s64;
    if (threadIdx.x == 0) {
        const long long* p = (const long long*)e;
        int is64 = 1;
        for (int t = 0; t < 16; t++) {
            long long v = p[t];
            if (v < 0 || v >= NN) is64 = 0;
        }
        s64 = is64;
    }
    __syncthreads();
    int f64 = s64;
    int i = blockIdx.x * blockDim.x + threadIdx.x;
    if (i < NE) {
        int s, d;
        if (f64) {
            const long long* p = (const long long*)e;
            s = (int)p[i]; d = (int)p[NE + i];
        } else {
            const int* p = (const int*)e;
            s = p[i]; d = p[NE + i];
        }
        g_src[i] = s;
        g_dst[i] = d;
        atomicAdd(&g_deg[d], 1);
    }
    if (i < NN) {
        if (f64) g_batch[i] = (int)((const long long*)b)[i];
        else     g_batch[i] = ((const int*)b)[i];
    }
}

// ---------------- CSR build ----------------
__global__ void k_scan1() {
    __shared__ int s[256];
    int tid = threadIdx.x;
    int i = blockIdx.x * 256 + tid;
    int v = (i < NN) ? g_deg[i] : 0;
    s[tid] = v;
#pragma unroll
    for (int off = 1; off < 256; off <<= 1) {
        __syncthreads();
        int t = (tid >= off) ? s[tid - off] : 0;
        __syncthreads();
        s[tid] += t;
    }
    __syncthreads();
    if (i < NN) g_rowptr[i] = s[tid] - v;
    if (tid == 255) g_blksum[blockIdx.x] = s[255];
}
__global__ void k_scan2() {
    __shared__ int s[512];
    int tid = threadIdx.x;
    int v = (tid < NBLK) ? g_blksum[tid] : 0;
    s[tid] = v;
#pragma unroll
    for (int off = 1; off < 512; off <<= 1) {
        __syncthreads();
        int t = (tid >= off) ? s[tid - off] : 0;
        __syncthreads();
        s[tid] += t;
    }
    __syncthreads();
    g_blkoff[tid] = s[tid] - v;
}
__global__ void k_scan3() {
    int i = blockIdx.x * 256 + threadIdx.x;
    if (i < NN) {
        g_rowptr[i] += g_blkoff[blockIdx.x];
        g_cursor[i] = 0;
        g_dinv[i] = rsqrtf((float)g_deg[i] + 1.0f);
    }
}
__global__ void k_csrfill() {
    int e = blockIdx.x * blockDim.x + threadIdx.x;
    if (e >= NE) return;
    int s = g_src[e], d = g_dst[e];
    int pos = atomicAdd(&g_cursor[d], 1);
    int slot = g_rowptr[d] + pos;
    g_csrc[slot] = s;
    g_cnrm[slot] = g_dinv[s] * g_dinv[d];
}

// ---------------- weight transposes + bf16 splits ----------------
__global__ void k_wsplit_all(const float* __restrict__ W1, const float* __restrict__ W2,
                             const float* __restrict__ W3) {
    int i = blockIdx.x * blockDim.x + threadIdx.x;
    const int N1 = 128 * 256;
    if (i < N1) {
        int k = i >> 8, n = i & 255;
        float v = W1[i];
        __nv_bfloat16 h = __float2bfloat16(v);
        g_w1hi[(size_t)n * 128 + k] = h;
        g_w1lo[(size_t)n * 128 + k] = __float2bfloat16(v - __bfloat162float(h));
        return;
    }
    i -= N1;
    const int N2 = 256 * 256;
    if (i < N2) {
        int k = i >> 8, n = i & 255;
        float v = W2[i];
        __nv_bfloat16 h = __float2bfloat16(v);
        g_w2hi[(size_t)n * 256 + k] = h;
        g_w2lo[(size_t)n * 256 + k] = __float2bfloat16(v - __bfloat162float(h));
        return;
    }
    i -= N2;
    if (i < N2) {
        int k = i >> 8, n = i & 255;
        float v = W3[i];
        __nv_bfloat16 h = __float2bfloat16(v);
        g_w3hi[(size_t)n * 256 + k] = h;
        g_w3lo[(size_t)n * 256 + k] = __float2bfloat16(v - __bfloat162float(h));
    }
}

// ---------------- x -> bf16 hi/lo ----------------
__global__ void k_xsplit(const float* __restrict__ x) {
    int i = blockIdx.x * blockDim.x + threadIdx.x;
    if (i >= NN * 32) return;
    float4 v = *(const float4*)(x + (size_t)i * 4);
    uint2 hp, lp;
    split4(v, hp, lp);
    ((uint2*)g_ahi)[i] = hp;
    ((uint2*)g_alo)[i] = lp;
}

// ---------------- pure-bf16 GEMM, K-chunk 32, 2 CTAs/SM ----------------
// stage layout (per buffer): Ahi @0, Alo @10240, Bhi @20480, Blo @30720
#define TSTR  40            // row stride in bf16 elems (32 + 8 pad)
#define SPLO  10240
#define SB_H  20480
#define SB_L  30720
#define STG   40960
#define GEMM_SMEM 81920

__global__ void __launch_bounds__(256, 2)
k_gemm(const __nv_bfloat16* __restrict__ ahi, const __nv_bfloat16* __restrict__ alo,
       const __nv_bfloat16* __restrict__ wt_hi, const __nv_bfloat16* __restrict__ wt_lo,
       float* __restrict__ outH, int M, int K)
{
    extern __shared__ char smem[];
    uint32_t sb = smem_u32(smem);
    int tid = threadIdx.x;
    int wid = tid >> 5;
    int lane = tid & 31;
    int bm = blockIdx.x * 128;
    int wm = (wid >> 2) * 64;
    int wn = (wid & 3) * 32;

    const int nch = K >> 5;          // 32-wide K chunks
    const int ntot = 2 * nch;        // x2 N-halves

#define STAGE(tt) do {                                                          \
        int nh2 = (tt) / nch, ch2 = (tt) % nch;                                 \
        int k0b = ch2 * 32, n0b = nh2 * 128;                                    \
        uint32_t base = sb + ((tt) & 1) * STG;                                  \
        _Pragma("unroll")                                                       \
        for (int it = 0; it < 2; it++) {                                        \
            int idx = tid + it * 256;                                           \
            int row = idx >> 2, g = idx & 3;                                    \
            uint32_t off = (uint32_t)(row * TSTR + g * 8) * 2;                  \
            size_t asrc = (size_t)(bm + row) * K + k0b + g * 8;                 \
            size_t bsrc = (size_t)(n0b + row) * K + k0b + g * 8;                \
            cp16(base + off,        ahi + asrc);                                \
            cp16(base + SPLO + off, alo + asrc);                                \
            cp16(base + SB_H + off, wt_hi + bsrc);                              \
            cp16(base + SB_L + off, wt_lo + bsrc);                              \
        }                                                                       \
        CP_COMMIT();                                                            \
    } while (0)

    STAGE(0);

    float acc[4][4][4];
#pragma unroll
    for (int mi = 0; mi < 4; mi++)
#pragma unroll
        for (int ni = 0; ni < 4; ni++)
#pragma unroll
            for (int q = 0; q < 4; q++) acc[mi][ni][q] = 0.0f;

    for (int t = 0; t < ntot; t++) {
        int nh = t / nch, ch = t % nch;

        if (t + 1 < ntot) { STAGE(t + 1); CP_WAIT(1); }
        else              { CP_WAIT(0); }
        __syncthreads();

        uint32_t base = sb + (t & 1) * STG;
#pragma unroll
        for (int ks = 0; ks < 2; ks++) {
            uint32_t ah[4][4], al[4][4], bh[2][4], bl[2][4];
            int arow = (lane & 15);
            int acol = ks * 16 + ((lane >> 4) << 3);
#pragma unroll
            for (int mi = 0; mi < 4; mi++) {
                uint32_t off = (uint32_t)((wm + mi * 16 + arow) * TSTR + acol) * 2;
                ldmat_x4(ah[mi], base + off);
                ldmat_x4(al[mi], base + SPLO + off);
            }
            int brow = ((lane >> 4) << 3) + (lane & 7);
            int bcol = ks * 16 + ((lane >> 3) & 1) * 8;
#pragma unroll
            for (int j = 0; j < 2; j++) {
                uint32_t off = (uint32_t)((wn + 16 * j + brow) * TSTR + bcol) * 2;
                ldmat_x4(bh[j], base + SB_H + off);
                ldmat_x4(bl[j], base + SB_L + off);
            }
#pragma unroll
            for (int mi = 0; mi < 4; mi++) {
#pragma unroll
                for (int ni = 0; ni < 4; ni++) {
                    const uint32_t* bhp = &bh[ni >> 1][(ni & 1) * 2];
                    const uint32_t* blp = &bl[ni >> 1][(ni & 1) * 2];
                    mma16816(acc[mi][ni], ah[mi], bhp);
                    mma16816(acc[mi][ni], ah[mi], blp);
                    mma16816(acc[mi][ni], al[mi], bhp);
                }
            }
        }

        if (ch == nch - 1) {
            int n0 = nh * 128;
            int g = lane >> 2, tg = lane & 3;
#pragma unroll
            for (int mi = 0; mi < 4; mi++) {
                int r0 = bm + wm + mi * 16 + g;
                int r1 = r0 + 8;
#pragma unroll
                for (int ni = 0; ni < 4; ni++) {
                    int col = n0 + wn + ni * 8 + tg * 2;
                    float* c = acc[mi][ni];
                    if (r0 < M)
                        *(float2*)(outH + (size_t)r0 * 256 + col) = make_float2(c[0], c[1]);
                    if (r1 < M)
                        *(float2*)(outH + (size_t)r1 * 256 + col) = make_float2(c[2], c[3]);
                    c[0] = c[1] = c[2] = c[3] = 0.f;
                }
            }
        }
        __syncthreads();
    }
#undef STAGE
}

// ---------------- CSR gather -> relu -> bf16 hi/lo ----------------
__global__ void __launch_bounds__(256) k_gather(const float* __restrict__ bias) {
    int node = blockIdx.x * 8 + (threadIdx.x >> 5);
    int lane = threadIdx.x & 31;
    if (node >= NN) return;
    int beg = g_rowptr[node];
    int dg  = g_deg[node];
    float di = g_dinv[node];
    float nrm2 = di * di;
    const float4* hrow = (const float4*)(g_bufH + (size_t)node * FDIM);
    const float4* bias4 = (const float4*)bias;
    float4 h0 = hrow[lane];
    float4 h1 = hrow[lane + 32];
    float4 b0 = __ldg(&bias4[lane]);
    float4 b1 = __ldg(&bias4[lane + 32]);
    float4 a0, a1;
    a0.x = h0.x * nrm2 + b0.x; a0.y = h0.y * nrm2 + b0.y;
    a0.z = h0.z * nrm2 + b0.z; a0.w = h0.w * nrm2 + b0.w;
    a1.x = h1.x * nrm2 + b1.x; a1.y = h1.y * nrm2 + b1.y;
    a1.z = h1.z * nrm2 + b1.z; a1.w = h1.w * nrm2 + b1.w;
    int j = 0;
    for (; j + 1 < dg; j += 2) {
        int s0 = __ldg(&g_csrc[beg + j]);
        int s1 = __ldg(&g_csrc[beg + j + 1]);
        float n0 = __ldg(&g_cnrm[beg + j]);
        float n1 = __ldg(&g_cnrm[beg + j + 1]);
        const float4* p0 = (const float4*)(g_bufH + (size_t)s0 * FDIM);
        const float4* p1 = (const float4*)(g_bufH + (size_t)s1 * FDIM);
        float4 u0 = p0[lane], u1 = p0[lane + 32];
        float4 w0 = p1[lane], w1 = p1[lane + 32];
        a0.x += u0.x * n0; a0.y += u0.y * n0; a0.z += u0.z * n0; a0.w += u0.w * n0;
        a1.x += u1.x * n0; a1.y += u1.y * n0; a1.z += u1.z * n0; a1.w += u1.w * n0;
        a0.x += w0.x * n1; a0.y += w0.y * n1; a0.z += w0.z * n1; a0.w += w0.w * n1;
        a1.x += w1.x * n1; a1.y += w1.y * n1; a1.z += w1.z * n1; a1.w += w1.w * n1;
    }
    if (j < dg) {
        int s = __ldg(&g_csrc[beg + j]);
        float nm = __ldg(&g_cnrm[beg + j]);
        const float4* p = (const float4*)(g_bufH + (size_t)s * FDIM);
        float4 v0 = p[lane], v1 = p[lane + 32];
        a0.x += v0.x * nm; a0.y += v0.y * nm; a0.z += v0.z * nm; a0.w += v0.w * nm;
        a1.x += v1.x * nm; a1.y += v1.y * nm; a1.z += v1.z * nm; a1.w += v1.w * nm;
    }
    a0.x = fmaxf(a0.x, 0.f); a0.y = fmaxf(a0.y, 0.f);
    a0.z = fmaxf(a0.z, 0.f); a0.w = fmaxf(a0.w, 0.f);
    a1.x = fmaxf(a1.x, 0.f); a1.y = fmaxf(a1.y, 0.f);
    a1.z = fmaxf(a1.z, 0.f); a1.w = fmaxf(a1.w, 0.f);
    uint2 hp0, lp0, hp1, lp1;
    split4(a0, hp0, lp0);
    split4(a1, hp1, lp1);
    uint2* hi = (uint2*)(g_ahi + (size_t)node * FDIM);
    uint2* lo = (uint2*)(g_alo + (size_t)node * FDIM);
    hi[lane]      = hp0;
    hi[lane + 32] = hp1;
    lo[lane]      = lp0;
    lo[lane + 32] = lp1;
}

// ---------------- fused pool + FC ----------------
__device__ __forceinline__ int lbound(const int* a, int n, int key) {
    int lo = 0, hi = n;
    while (lo < hi) { int m = (lo + hi) >> 1; if (a[m] < key) lo = m + 1; else hi = m; }
    return lo;
}

__global__ void k_poolfc(const float* __restrict__ Wfc, const float* __restrict__ bfc,
                         float* __restrict__ out) {
    __shared__ float sp[FDIM];
    __shared__ int bnd[2];
    int g = blockIdx.x;
    int t = threadIdx.x;
    if (t == 0) bnd[0] = lbound(g_batch, NN, g);
    if (t == 1) bnd[1] = lbound(g_batch, NN, g + 1);
    __syncthreads();
    int lo = bnd[0], hi = bnd[1];
    float acc = 0.f;
    for (int n = lo; n < hi; n++) {
        float v = __bfloat162float(g_ahi[(size_t)n * FDIM + t]) +
                  __bfloat162float(g_alo[(size_t)n * FDIM + t]);
        acc += fmaxf(v, 0.f);
    }
    int cnt = hi - lo;
    sp[t] = cnt > 0 ? acc / (float)cnt : 0.f;
    __syncthreads();
    if (t < FOUT) {
        float o = bfc[t];
#pragma unroll 4
        for (int f = 0; f < FDIM; f++) o += sp[f] * Wfc[(size_t)f * FOUT + t];
        out[(size_t)g * FOUT + t] = o;
    }
}

// ---------------- launch ----------------
extern "C" void kernel_launch(void* const* d_in, const int* in_sizes, int n_in,
                              void* d_out, int out_size) {
    (void)in_sizes; (void)n_in; (void)out_size;
    const float* x   = (const float*)d_in[0];
    const void*  ei  = d_in[1];
    const void*  bt  = d_in[2];
    const float* W1  = (const float*)d_in[3];
    const float* b1  = (const float*)d_in[4];
    const float* W2  = (const float*)d_in[5];
    const float* b2  = (const float*)d_in[6];
    const float* W3  = (const float*)d_in[7];
    const float* b3  = (const float*)d_in[8];
    const float* Wfc = (const float*)d_in[9];
    const float* bfc = (const float*)d_in[10];
    float* out = (float*)d_out;

    float* bufH = nullptr;
    cudaGetSymbolAddress((void**)&bufH, g_bufH);
    __nv_bfloat16 *ahi, *alo, *w1h, *w1l, *w2h, *w2l, *w3h, *w3l;
    cudaGetSymbolAddress((void**)&ahi, g_ahi);
    cudaGetSymbolAddress((void**)&alo, g_alo);
    cudaGetSymbolAddress((void**)&w1h, g_w1hi);
    cudaGetSymbolAddress((void**)&w1l, g_w1lo);
    cudaGetSymbolAddress((void**)&w2h, g_w2hi);
    cudaGetSymbolAddress((void**)&w2l, g_w2lo);
    cudaGetSymbolAddress((void**)&w3h, g_w3hi);
    cudaGetSymbolAddress((void**)&w3l, g_w3lo);

    cudaFuncSetAttribute(k_gemm, cudaFuncAttributeMaxDynamicSharedMemorySize, GEMM_SMEM);

    k_zero<<<NBLK, 256>>>();
    k_prep<<<(NE + 255) / 256, 256>>>(ei, bt);
    k_scan1<<<NBLK, 256>>>();
    k_scan2<<<1, 512>>>();
    k_scan3<<<NBLK, 256>>>();
    k_csrfill<<<(NE + 255) / 256, 256>>>();
    k_wsplit_all<<<(128 * 256 + 2 * 256 * 256 + 255) / 256, 256>>>(W1, W2, W3);
    k_xsplit<<<(NN * 32 + 255) / 256, 256>>>(x);

    const int gemm_grid = (NN + 127) / 128;
    const int gat_grid  = (NN + 7) / 8;

    k_gemm<<<gemm_grid, 256, GEMM_SMEM>>>(ahi, alo, w1h, w1l, bufH, NN, 128);
    k_gather<<<gat_grid, 256>>>(b1);
    k_gemm<<<gemm_grid, 256, GEMM_SMEM>>>(ahi, alo, w2h, w2l, bufH, NN, 256);
    k_gather<<<gat_grid, 256>>>(b2);
    k_gemm<<<gemm_grid, 256, GEMM_SMEM>>>(ahi, alo, w3h, w3l, bufH, NN, 256);
    k_gather<<<gat_grid, 256>>>(b3);

    k_poolfc<<<NG, FDIM>>>(Wfc, bfc, out);
}

// round 10
// speedup vs baseline: 2.7744x; 1.0119x over previous
#include <cuda_runtime.h>
#include <cuda_bf16.h>
#include <math.h>
#include <stdint.h>

#define NN 100000
#define NE 320000
#define NG 512
#define FDIM 256
#define FOUT 128
#define NBLK 391   // ceil(NN/256)

// ---------------- scratch (static device memory; no allocation) ----------------
__device__ __align__(16) float g_bufH[(size_t)NN * FDIM];
__device__ __align__(16) __nv_bfloat16 g_ahi[(size_t)(NN + 128) * FDIM];
__device__ __align__(16) __nv_bfloat16 g_alo[(size_t)(NN + 128) * FDIM];
__device__ float g_dinv[NN];
__device__ int   g_deg[NN];
__device__ int   g_rowptr[NN];
__device__ int   g_cursor[NN];
__device__ int   g_blksum[512];
__device__ int   g_blkoff[512];
__device__ int   g_csrc[NE];
__device__ float g_cnrm[NE];
__device__ int   g_src[NE];
__device__ int   g_dst[NE];
__device__ int   g_batch[NN];
__device__ __align__(16) __nv_bfloat16 g_w1hi[128 * 256];
__device__ __align__(16) __nv_bfloat16 g_w1lo[128 * 256];
__device__ __align__(16) __nv_bfloat16 g_w2hi[256 * 256];
__device__ __align__(16) __nv_bfloat16 g_w2lo[256 * 256];
__device__ __align__(16) __nv_bfloat16 g_w3hi[256 * 256];
__device__ __align__(16) __nv_bfloat16 g_w3lo[256 * 256];

// ---------------- helpers ----------------
__device__ __forceinline__ uint32_t smem_u32(const void* p) {
    uint32_t a;
    asm("{ .reg .u64 t; cvta.to.shared.u64 t, %1; cvt.u32.u64 %0, t; }" : "=r"(a) : "l"(p));
    return a;
}
__device__ __forceinline__ void ldmat_x4(uint32_t* r, uint32_t addr) {
    asm volatile("ldmatrix.sync.aligned.m8n8.x4.shared.b16 {%0,%1,%2,%3}, [%4];"
                 : "=r"(r[0]), "=r"(r[1]), "=r"(r[2]), "=r"(r[3]) : "r"(addr));
}
__device__ __forceinline__ void mma16816(float* c, const uint32_t* a, const uint32_t* b) {
    asm volatile("mma.sync.aligned.m16n8k16.row.col.f32.bf16.bf16.f32 "
                 "{%0,%1,%2,%3}, {%4,%5,%6,%7}, {%8,%9}, {%0,%1,%2,%3};"
                 : "+f"(c[0]), "+f"(c[1]), "+f"(c[2]), "+f"(c[3])
                 : "r"(a[0]), "r"(a[1]), "r"(a[2]), "r"(a[3]), "r"(b[0]), "r"(b[1]));
}
__device__ __forceinline__ void cp16(uint32_t smem_addr, const void* gptr) {
    asm volatile("cp.async.cg.shared.global [%0], [%1], 16;" :: "r"(smem_addr), "l"(gptr));
}
#define CP_COMMIT() asm volatile("cp.async.commit_group;" ::: "memory")
#define CP_WAIT(n)  asm volatile("cp.async.wait_group %0;" :: "n"(n) : "memory")

// PDL controls (no-op when not PDL-launched)
__device__ __forceinline__ void gdc_wait()   { asm volatile("griddepcontrol.wait;" ::: "memory"); }
__device__ __forceinline__ void gdc_launch() { asm volatile("griddepcontrol.launch_dependents;" ::: "memory"); }

// streaming store (evict-first): keep L2 for A operands
__device__ __forceinline__ void stcs2(float* p, float a, float b) {
    asm volatile("st.global.cs.v2.f32 [%0], {%1,%2};" :: "l"(p), "f"(a), "f"(b) : "memory");
}

__device__ __forceinline__ void split4(float4 v, uint2& hp, uint2& lp) {
    __nv_bfloat16 h0 = __float2bfloat16(v.x), h1 = __float2bfloat16(v.y);
    __nv_bfloat16 h2 = __float2bfloat16(v.z), h3 = __float2bfloat16(v.w);
    __nv_bfloat16 l0 = __float2bfloat16(v.x - __bfloat162float(h0));
    __nv_bfloat16 l1 = __float2bfloat16(v.y - __bfloat162float(h1));
    __nv_bfloat16 l2 = __float2bfloat16(v.z - __bfloat162float(h2));
    __nv_bfloat16 l3 = __float2bfloat16(v.w - __bfloat162float(h3));
    hp.x = ((uint32_t)__bfloat16_as_ushort(h1) << 16) | __bfloat16_as_ushort(h0);
    hp.y = ((uint32_t)__bfloat16_as_ushort(h3) << 16) | __bfloat16_as_ushort(h2);
    lp.x = ((uint32_t)__bfloat16_as_ushort(l1) << 16) | __bfloat16_as_ushort(l0);
    lp.y = ((uint32_t)__bfloat16_as_ushort(l3) << 16) | __bfloat16_as_ushort(l2);
}

// ---------------- prep ----------------
__global__ void k_zero() {
    int i = blockIdx.x * blockDim.x + threadIdx.x;
    if (i < NN) g_deg[i] = 0;
}

__global__ void k_prep(const void* e, const void* b) {
    __shared__ int s64;
    if (threadIdx.x == 0) {
        const long long* p = (const long long*)e;
        int is64 = 1;
        for (int t = 0; t < 16; t++) {
            long long v = p[t];
            if (v < 0 || v >= NN) is64 = 0;
        }
        s64 = is64;
    }
    __syncthreads();
    int f64 = s64;
    int i = blockIdx.x * blockDim.x + threadIdx.x;
    if (i < NE) {
        int s, d;
        if (f64) {
            const long long* p = (const long long*)e;
            s = (int)p[i]; d = (int)p[NE + i];
        } else {
            const int* p = (const int*)e;
            s = p[i]; d = p[NE + i];
        }
        g_src[i] = s;
        g_dst[i] = d;
        atomicAdd(&g_deg[d], 1);
    }
    if (i < NN) {
        if (f64) g_batch[i] = (int)((const long long*)b)[i];
        else     g_batch[i] = ((const int*)b)[i];
    }
}

// ---------------- CSR build ----------------
__global__ void k_scan1() {
    __shared__ int s[256];
    int tid = threadIdx.x;
    int i = blockIdx.x * 256 + tid;
    int v = (i < NN) ? g_deg[i] : 0;
    s[tid] = v;
#pragma unroll
    for (int off = 1; off < 256; off <<= 1) {
        __syncthreads();
        int t = (tid >= off) ? s[tid - off] : 0;
        __syncthreads();
        s[tid] += t;
    }
    __syncthreads();
    if (i < NN) g_rowptr[i] = s[tid] - v;
    if (tid == 255) g_blksum[blockIdx.x] = s[255];
}
__global__ void k_scan2() {
    __shared__ int s[512];
    int tid = threadIdx.x;
    int v = (tid < NBLK) ? g_blksum[tid] : 0;
    s[tid] = v;
#pragma unroll
    for (int off = 1; off < 512; off <<= 1) {
        __syncthreads();
        int t = (tid >= off) ? s[tid - off] : 0;
        __syncthreads();
        s[tid] += t;
    }
    __syncthreads();
    g_blkoff[tid] = s[tid] - v;
}
__global__ void k_scan3() {
    int i = blockIdx.x * 256 + threadIdx.x;
    if (i < NN) {
        g_rowptr[i] += g_blkoff[blockIdx.x];
        g_cursor[i] = 0;
        g_dinv[i] = rsqrtf((float)g_deg[i] + 1.0f);
    }
}
__global__ void k_csrfill() {
    int e = blockIdx.x * blockDim.x + threadIdx.x;
    if (e >= NE) return;
    int s = g_src[e], d = g_dst[e];
    int pos = atomicAdd(&g_cursor[d], 1);
    int slot = g_rowptr[d] + pos;
    g_csrc[slot] = s;
    g_cnrm[slot] = g_dinv[s] * g_dinv[d];
}

// ---------------- merged input/weight split ----------------
__global__ void k_split(const float* __restrict__ x, const float* __restrict__ W1,
                        const float* __restrict__ W2, const float* __restrict__ W3) {
    int i = blockIdx.x * blockDim.x + threadIdx.x;
    const int NX = NN * 32;           // x float4 chunks
    if (i < NX) {
        float4 v = *(const float4*)(x + (size_t)i * 4);
        uint2 hp, lp;
        split4(v, hp, lp);
        ((uint2*)g_ahi)[i] = hp;
        ((uint2*)g_alo)[i] = lp;
        return;
    }
    i -= NX;
    const int N1 = 128 * 256;
    if (i < N1) {
        int k = i >> 8, n = i & 255;
        float v = W1[i];
        __nv_bfloat16 h = __float2bfloat16(v);
        g_w1hi[(size_t)n * 128 + k] = h;
        g_w1lo[(size_t)n * 128 + k] = __float2bfloat16(v - __bfloat162float(h));
        return;
    }
    i -= N1;
    const int N2 = 256 * 256;
    if (i < N2) {
        int k = i >> 8, n = i & 255;
        float v = W2[i];
        __nv_bfloat16 h = __float2bfloat16(v);
        g_w2hi[(size_t)n * 256 + k] = h;
        g_w2lo[(size_t)n * 256 + k] = __float2bfloat16(v - __bfloat162float(h));
        return;
    }
    i -= N2;
    if (i < N2) {
        int k = i >> 8, n = i & 255;
        float v = W3[i];
        __nv_bfloat16 h = __float2bfloat16(v);
        g_w3hi[(size_t)n * 256 + k] = h;
        g_w3lo[(size_t)n * 256 + k] = __float2bfloat16(v - __bfloat162float(h));
    }
}

// ---------------- pure-bf16 GEMM, K-chunk 32, 2 CTAs/SM, PDL ----------------
#define TSTR  40
#define SPLO  10240
#define SB_H  20480
#define SB_L  30720
#define STG   40960
#define GEMM_SMEM 81920

__global__ void __launch_bounds__(256, 2)
k_gemm(const __nv_bfloat16* __restrict__ ahi, const __nv_bfloat16* __restrict__ alo,
       const __nv_bfloat16* __restrict__ wt_hi, const __nv_bfloat16* __restrict__ wt_lo,
       float* __restrict__ outH, int M, int K)
{
    extern __shared__ char smem[];
    uint32_t sb = smem_u32(smem);
    int tid = threadIdx.x;
    int wid = tid >> 5;
    int lane = tid & 31;
    int bm = blockIdx.x * 128;
    int wm = (wid >> 2) * 64;
    int wn = (wid & 3) * 32;

    const int nch = K >> 5;
    const int ntot = 2 * nch;

    // wait for producer (previous gather) before reading ahi/alo
    gdc_wait();

#define STAGE(tt) do {                                                          \
        int nh2 = (tt) / nch, ch2 = (tt) % nch;                                 \
        int k0b = ch2 * 32, n0b = nh2 * 128;                                    \
        uint32_t base = sb + ((tt) & 1) * STG;                                  \
        _Pragma("unroll")                                                       \
        for (int it = 0; it < 2; it++) {                                        \
            int idx = tid + it * 256;                                           \
            int row = idx >> 2, g = idx & 3;                                    \
            uint32_t off = (uint32_t)(row * TSTR + g * 8) * 2;                  \
            size_t asrc = (size_t)(bm + row) * K + k0b + g * 8;                 \
            size_t bsrc = (size_t)(n0b + row) * K + k0b + g * 8;                \
            cp16(base + off,        ahi + asrc);                                \
            cp16(base + SPLO + off, alo + asrc);                                \
            cp16(base + SB_H + off, wt_hi + bsrc);                              \
            cp16(base + SB_L + off, wt_lo + bsrc);                              \
        }                                                                       \
        CP_COMMIT();                                                            \
    } while (0)

    STAGE(0);

    float acc[4][4][4];
#pragma unroll
    for (int mi = 0; mi < 4; mi++)
#pragma unroll
        for (int ni = 0; ni < 4; ni++)
#pragma unroll
            for (int q = 0; q < 4; q++) acc[mi][ni][q] = 0.0f;

    for (int t = 0; t < ntot; t++) {
        int nh = t / nch, ch = t % nch;

        if (t + 1 < ntot) { STAGE(t + 1); CP_WAIT(1); }
        else              { CP_WAIT(0); }
        __syncthreads();

        uint32_t base = sb + (t & 1) * STG;
#pragma unroll
        for (int ks = 0; ks < 2; ks++) {
            uint32_t ah[4][4], al[4][4], bh[2][4], bl[2][4];
            int arow = (lane & 15);
            int acol = ks * 16 + ((lane >> 4) << 3);
#pragma unroll
            for (int mi = 0; mi < 4; mi++) {
                uint32_t off = (uint32_t)((wm + mi * 16 + arow) * TSTR + acol) * 2;
                ldmat_x4(ah[mi], base + off);
                ldmat_x4(al[mi], base + SPLO + off);
            }
            int brow = ((lane >> 4) << 3) + (lane & 7);
            int bcol = ks * 16 + ((lane >> 3) & 1) * 8;
#pragma unroll
            for (int j = 0; j < 2; j++) {
                uint32_t off = (uint32_t)((wn + 16 * j + brow) * TSTR + bcol) * 2;
                ldmat_x4(bh[j], base + SB_H + off);
                ldmat_x4(bl[j], base + SB_L + off);
            }
#pragma unroll
            for (int mi = 0; mi < 4; mi++) {
#pragma unroll
                for (int ni = 0; ni < 4; ni++) {
                    const uint32_t* bhp = &bh[ni >> 1][(ni & 1) * 2];
                    const uint32_t* blp = &bl[ni >> 1][(ni & 1) * 2];
                    mma16816(acc[mi][ni], ah[mi], bhp);
                    mma16816(acc[mi][ni], ah[mi], blp);
                    mma16816(acc[mi][ni], al[mi], bhp);
                }
            }
        }

        // let the dependent (gather) start its prologue while we do the last epilogue
        if (t == ntot - 1) gdc_launch();

        if (ch == nch - 1) {
            int n0 = nh * 128;
            int g = lane >> 2, tg = lane & 3;
#pragma unroll
            for (int mi = 0; mi < 4; mi++) {
                int r0 = bm + wm + mi * 16 + g;
                int r1 = r0 + 8;
#pragma unroll
                for (int ni = 0; ni < 4; ni++) {
                    int col = n0 + wn + ni * 8 + tg * 2;
                    float* c = acc[mi][ni];
                    if (r0 < M) stcs2(outH + (size_t)r0 * 256 + col, c[0], c[1]);
                    if (r1 < M) stcs2(outH + (size_t)r1 * 256 + col, c[2], c[3]);
                    c[0] = c[1] = c[2] = c[3] = 0.f;
                }
            }
        }
        __syncthreads();
    }
#undef STAGE
}

// ---------------- CSR gather -> relu -> bf16 hi/lo (PDL) ----------------
__global__ void __launch_bounds__(256) k_gather(const float* __restrict__ bias) {
    int node = blockIdx.x * 8 + (threadIdx.x >> 5);
    int lane = threadIdx.x & 31;
    if (node >= NN) { gdc_wait(); return; }
    // --- prologue: everything independent of the producer GEMM ---
    int beg = g_rowptr[node];
    int dg  = g_deg[node];
    float di = g_dinv[node];
    float nrm2 = di * di;
    const float4* bias4 = (const float4*)bias;
    float4 b0 = __ldg(&bias4[lane]);
    float4 b1 = __ldg(&bias4[lane + 32]);
    // --- wait for GEMM's H ---
    gdc_wait();
    const float4* hrow = (const float4*)(g_bufH + (size_t)node * FDIM);
    float4 h0 = hrow[lane];
    float4 h1 = hrow[lane + 32];
    float4 a0, a1;
    a0.x = h0.x * nrm2 + b0.x; a0.y = h0.y * nrm2 + b0.y;
    a0.z = h0.z * nrm2 + b0.z; a0.w = h0.w * nrm2 + b0.w;
    a1.x = h1.x * nrm2 + b1.x; a1.y = h1.y * nrm2 + b1.y;
    a1.z = h1.z * nrm2 + b1.z; a1.w = h1.w * nrm2 + b1.w;
    int j = 0;
    for (; j + 1 < dg; j += 2) {
        int s0 = __ldg(&g_csrc[beg + j]);
        int s1 = __ldg(&g_csrc[beg + j + 1]);
        float n0 = __ldg(&g_cnrm[beg + j]);
        float n1 = __ldg(&g_cnrm[beg + j + 1]);
        const float4* p0 = (const float4*)(g_bufH + (size_t)s0 * FDIM);
        const float4* p1 = (const float4*)(g_bufH + (size_t)s1 * FDIM);
        float4 u0 = p0[lane], u1 = p0[lane + 32];
        float4 w0 = p1[lane], w1 = p1[lane + 32];
        a0.x += u0.x * n0; a0.y += u0.y * n0; a0.z += u0.z * n0; a0.w += u0.w * n0;
        a1.x += u1.x * n0; a1.y += u1.y * n0; a1.z += u1.z * n0; a1.w += u1.w * n0;
        a0.x += w0.x * n1; a0.y += w0.y * n1; a0.z += w0.z * n1; a0.w += w0.w * n1;
        a1.x += w1.x * n1; a1.y += w1.y * n1; a1.z += w1.z * n1; a1.w += w1.w * n1;
    }
    if (j < dg) {
        int s = __ldg(&g_csrc[beg + j]);
        float nm = __ldg(&g_cnrm[beg + j]);
        const float4* p = (const float4*)(g_bufH + (size_t)s * FDIM);
        float4 v0 = p[lane], v1 = p[lane + 32];
        a0.x += v0.x * nm; a0.y += v0.y * nm; a0.z += v0.z * nm; a0.w += v0.w * nm;
        a1.x += v1.x * nm; a1.y += v1.y * nm; a1.z += v1.z * nm; a1.w += v1.w * nm;
    }
    gdc_launch();   // next GEMM may start its prologue
    a0.x = fmaxf(a0.x, 0.f); a0.y = fmaxf(a0.y, 0.f);
    a0.z = fmaxf(a0.z, 0.f); a0.w = fmaxf(a0.w, 0.f);
    a1.x = fmaxf(a1.x, 0.f); a1.y = fmaxf(a1.y, 0.f);
    a1.z = fmaxf(a1.z, 0.f); a1.w = fmaxf(a1.w, 0.f);
    uint2 hp0, lp0, hp1, lp1;
    split4(a0, hp0, lp0);
    split4(a1, hp1, lp1);
    uint2* hi = (uint2*)(g_ahi + (size_t)node * FDIM);
    uint2* lo = (uint2*)(g_alo + (size_t)node * FDIM);
    hi[lane]      = hp0;
    hi[lane + 32] = hp1;
    lo[lane]      = lp0;
    lo[lane + 32] = lp1;
}

// ---------------- fused pool + FC (PDL) ----------------
__device__ __forceinline__ int lbound(const int* a, int n, int key) {
    int lo = 0, hi = n;
    while (lo < hi) { int m = (lo + hi) >> 1; if (a[m] < key) lo = m + 1; else hi = m; }
    return lo;
}

__global__ void k_poolfc(const float* __restrict__ Wfc, const float* __restrict__ bfc,
                         float* __restrict__ out) {
    __shared__ float sp[FDIM];
    __shared__ int bnd[2];
    int g = blockIdx.x;
    int t = threadIdx.x;
    if (t == 0) bnd[0] = lbound(g_batch, NN, g);
    if (t == 1) bnd[1] = lbound(g_batch, NN, g + 1);
    __syncthreads();
    gdc_wait();
    int lo = bnd[0], hi = bnd[1];
    float acc = 0.f;
    for (int n = lo; n < hi; n++) {
        float v = __bfloat162float(g_ahi[(size_t)n * FDIM + t]) +
                  __bfloat162float(g_alo[(size_t)n * FDIM + t]);
        acc += fmaxf(v, 0.f);
    }
    int cnt = hi - lo;
    sp[t] = cnt > 0 ? acc / (float)cnt : 0.f;
    __syncthreads();
    if (t < FOUT) {
        float o = bfc[t];
#pragma unroll 4
        for (int f = 0; f < FDIM; f++) o += sp[f] * Wfc[(size_t)f * FOUT + t];
        out[(size_t)g * FOUT + t] = o;
    }
}

// ---------------- PDL launch helper ----------------
static void pdl_launch(const void* fn, int grid, int block, size_t smem, void** args) {
    cudaLaunchConfig_t cfg = {};
    cfg.gridDim = dim3((unsigned)grid, 1, 1);
    cfg.blockDim = dim3((unsigned)block, 1, 1);
    cfg.dynamicSmemBytes = smem;
    cfg.stream = 0;
    static cudaLaunchAttribute attr[1];
    attr[0].id = cudaLaunchAttributeProgrammaticStreamSerialization;
    attr[0].val.programmaticStreamSerializationAllowed = 1;
    cfg.attrs = attr;
    cfg.numAttrs = 1;
    cudaLaunchKernelExC(&cfg, fn, args);
}

// ---------------- launch ----------------
extern "C" void kernel_launch(void* const* d_in, const int* in_sizes, int n_in,
                              void* d_out, int out_size) {
    (void)in_sizes; (void)n_in; (void)out_size;
    const float* x   = (const float*)d_in[0];
    const void*  ei  = d_in[1];
    const void*  bt  = d_in[2];
    const float* W1  = (const float*)d_in[3];
    const float* b1  = (const float*)d_in[4];
    const float* W2  = (const float*)d_in[5];
    const float* b2  = (const float*)d_in[6];
    const float* W3  = (const float*)d_in[7];
    const float* b3  = (const float*)d_in[8];
    const float* Wfc = (const float*)d_in[9];
    const float* bfc = (const float*)d_in[10];
    float* out = (float*)d_out;

    float* bufH = nullptr;
    cudaGetSymbolAddress((void**)&bufH, g_bufH);
    __nv_bfloat16 *ahi, *alo, *w1h, *w1l, *w2h, *w2l, *w3h, *w3l;
    cudaGetSymbolAddress((void**)&ahi, g_ahi);
    cudaGetSymbolAddress((void**)&alo, g_alo);
    cudaGetSymbolAddress((void**)&w1h, g_w1hi);
    cudaGetSymbolAddress((void**)&w1l, g_w1lo);
    cudaGetSymbolAddress((void**)&w2h, g_w2hi);
    cudaGetSymbolAddress((void**)&w2l, g_w2lo);
    cudaGetSymbolAddress((void**)&w3h, g_w3hi);
    cudaGetSymbolAddress((void**)&w3l, g_w3lo);

    cudaFuncSetAttribute(k_gemm, cudaFuncAttributeMaxDynamicSharedMemorySize, GEMM_SMEM);

    // strictly serial prep (normal launches = full barriers)
    k_zero<<<NBLK, 256>>>();
    k_prep<<<(NE + 255) / 256, 256>>>(ei, bt);
    k_scan1<<<NBLK, 256>>>();
    k_scan2<<<1, 512>>>();
    k_scan3<<<NBLK, 256>>>();
    k_csrfill<<<(NE + 255) / 256, 256>>>();
    const int split_grid = (NN * 32 + 128 * 256 + 2 * 256 * 256 + 255) / 256;
    k_split<<<split_grid, 256>>>(x, W1, W2, W3);

    const int gemm_grid = (NN + 127) / 128;
    const int gat_grid  = (NN + 7) / 8;
    int M = NN;
    int K1 = 128, K2 = 256;

    // layer 1: normal GEMM launch (full barrier after prep), then PDL chain
    k_gemm<<<gemm_grid, 256, GEMM_SMEM>>>(ahi, alo, w1h, w1l, bufH, NN, 128);
    { void* a[] = { (void*)&b1 };
      pdl_launch((const void*)k_gather, gat_grid, 256, 0, a); }
    { void* a[] = { (void*)&ahi, (void*)&alo, (void*)&w2h, (void*)&w2l, (void*)&bufH, (void*)&M, (void*)&K2 };
      pdl_launch((const void*)k_gemm, gemm_grid, 256, GEMM_SMEM, a); }
    { void* a[] = { (void*)&b2 };
      pdl_launch((const void*)k_gather, gat_grid, 256, 0, a); }
    { void* a[] = { (void*)&ahi, (void*)&alo, (void*)&w3h, (void*)&w3l, (void*)&bufH, (void*)&M, (void*)&K2 };
      pdl_launch((const void*)k_gemm, gemm_grid, 256, GEMM_SMEM, a); }
    { void* a[] = { (void*)&b3 };
      pdl_launch((const void*)k_gather, gat_grid, 256, 0, a); }
    { void* a[] = { (void*)&Wfc, (void*)&bfc, (void*)&out };
      pdl_launch((const void*)k_poolfc, NG, FDIM, 0, a); }
    (void)K1;
}